// round 6
// baseline (speedup 1.0000x reference)
#include <cuda_runtime.h>
#include <cuda_bf16.h>
#include <math.h>
#include <stdint.h>

#define TDIM 2048
#define CDIM 1024
#define HN   8
#define NW   8192
#define WIN  448
#define KQ   512
#define TT   64
#define NTIL 32
#define GAMMA 0.96875f

// int8 15-bit fixed-point operands for the projection
__device__ int8_t g_X1[(size_t)TDIM * CDIM];
__device__ int8_t g_X0[(size_t)TDIM * CDIM];
__device__ int8_t g_W1[(size_t)3 * NW * CDIM];                 // [z][n][k]
__device__ int8_t g_W0[(size_t)3 * NW * CDIM];
__device__ float  g_sx[TDIM];                                  // rowmax/16256
__device__ float  g_gw[3 * NW];                                // colmax/16256

// bf16 hi/lo split tensors for attention
__device__ __nv_bfloat16 g_Qhi[(size_t)HN * TDIM * CDIM];
__device__ __nv_bfloat16 g_Qlo[(size_t)HN * TDIM * CDIM];
__device__ __nv_bfloat16 g_Khi[(size_t)HN * TDIM * CDIM];
__device__ __nv_bfloat16 g_Klo[(size_t)HN * TDIM * CDIM];
__device__ __nv_bfloat16 g_Vhi[(size_t)HN * TDIM * CDIM];      // [h][t][c]
__device__ __nv_bfloat16 g_Vlo[(size_t)HN * TDIM * CDIM];
__device__ __nv_bfloat16 g_Vthi[(size_t)HN * CDIM * TDIM];     // [h][c][t]
__device__ __nv_bfloat16 g_Vtlo[(size_t)HN * CDIM * TDIM];
__device__ __nv_bfloat16 g_Phi[(size_t)HN * NTIL * TT * KQ];   // [h][tile][t][q]
__device__ __nv_bfloat16 g_Plo[(size_t)HN * NTIL * TT * KQ];

// ---------------------------------------------------------------------------
#define CP16(dst, src) \
    asm volatile("cp.async.cg.shared.global [%0], [%1], 16;" :: "r"(dst), "l"(src))
#define CP16Z(dst, src, sz) \
    asm volatile("cp.async.cg.shared.global [%0], [%1], 16, %2;" :: "r"(dst), "l"(src), "r"(sz))
#define CP_COMMIT() asm volatile("cp.async.commit_group;" ::: "memory")
#define CP_WAIT1()  asm volatile("cp.async.wait_group 1;" ::: "memory")
#define CP_WAIT0()  asm volatile("cp.async.wait_group 0;" ::: "memory")

__device__ __forceinline__ uint32_t smem_u32(const void* p) {
    uint32_t a;
    asm("{ .reg .u64 t; cvta.to.shared.u64 t, %1; cvt.u32.u64 %0, t; }"
        : "=r"(a) : "l"(p));
    return a;
}

__device__ __forceinline__ void mma_bf16(float c[4], const uint32_t a[4],
                                         const uint32_t b[2]) {
    asm volatile(
        "mma.sync.aligned.m16n8k16.row.col.f32.bf16.bf16.f32 "
        "{%0,%1,%2,%3}, {%4,%5,%6,%7}, {%8,%9}, {%0,%1,%2,%3};"
        : "+f"(c[0]), "+f"(c[1]), "+f"(c[2]), "+f"(c[3])
        : "r"(a[0]), "r"(a[1]), "r"(a[2]), "r"(a[3]), "r"(b[0]), "r"(b[1]));
}

__device__ __forceinline__ void mma_s8(int c[4], const uint32_t a[4],
                                       const uint32_t b[2]) {
    asm volatile(
        "mma.sync.aligned.m16n8k32.row.col.s32.s8.s8.s32 "
        "{%0,%1,%2,%3}, {%4,%5,%6,%7}, {%8,%9}, {%0,%1,%2,%3};"
        : "+r"(c[0]), "+r"(c[1]), "+r"(c[2]), "+r"(c[3])
        : "r"(a[0]), "r"(a[1]), "r"(a[2]), "r"(a[3]), "r"(b[0]), "r"(b[1]));
}

// split two fp32 into packed hi/lo bf16 pairs
__device__ __forceinline__ uint32_t pack_bf2(float v0, float v1, uint32_t& lo) {
    __nv_bfloat16 h0 = __float2bfloat16(v0);
    __nv_bfloat16 h1 = __float2bfloat16(v1);
    __nv_bfloat16 l0 = __float2bfloat16(v0 - __bfloat162float(h0));
    __nv_bfloat16 l1 = __float2bfloat16(v1 - __bfloat162float(h1));
    lo = (uint32_t)*(unsigned short*)&l0 | ((uint32_t)*(unsigned short*)&l1 << 16);
    return (uint32_t)*(unsigned short*)&h0 | ((uint32_t)*(unsigned short*)&h1 << 16);
}

__device__ __forceinline__ void split15(float x, float S, int8_t& hi, int8_t& lo) {
    int q = (int)rintf(x * S);
    int h = (q + 64) >> 7;
    if (h > 127) h = 127;
    if (h < -128) h = -128;
    hi = (int8_t)h;
    lo = (int8_t)(q - (h << 7));
}

// ---------------------------------------------------------------------------
// Prep: X -> int8 15-bit split with per-row scale
// ---------------------------------------------------------------------------
__global__ __launch_bounds__(256) void prep_x_i8(const float* __restrict__ X)
{
    const int t = blockIdx.x;
    const int tid = threadIdx.x;
    __shared__ float red[256];

    float4 v = ((const float4*)(X + (size_t)t * CDIM))[tid];
    float m = fmaxf(fmaxf(fabsf(v.x), fabsf(v.y)), fmaxf(fabsf(v.z), fabsf(v.w)));
    red[tid] = m;
    __syncthreads();
#pragma unroll
    for (int off = 128; off > 0; off >>= 1) {
        if (tid < off) red[tid] = fmaxf(red[tid], red[tid + off]);
        __syncthreads();
    }
    const float rowmax = red[0] + 1e-30f;
    const float S = 16256.f / rowmax;

    int8_t h[4], l[4];
    split15(v.x, S, h[0], l[0]); split15(v.y, S, h[1], l[1]);
    split15(v.z, S, h[2], l[2]); split15(v.w, S, h[3], l[3]);
    ((char4*)(g_X1 + (size_t)t * CDIM))[tid] = make_char4(h[0], h[1], h[2], h[3]);
    ((char4*)(g_X0 + (size_t)t * CDIM))[tid] = make_char4(l[0], l[1], l[2], l[3]);
    if (tid == 0) g_sx[t] = rowmax / 16256.f;
}

// ---------------------------------------------------------------------------
// Prep: per-column |max| of W
// ---------------------------------------------------------------------------
__global__ __launch_bounds__(256) void prep_wmax(
    const float* __restrict__ Wq, const float* __restrict__ Wk,
    const float* __restrict__ Wv)
{
    const int z = blockIdx.y;
    const float* W = (z == 0) ? Wq : ((z == 1) ? Wk : Wv);
    const int n = blockIdx.x * 256 + threadIdx.x;
    float m = 0.f;
    for (int k = 0; k < CDIM; k++)
        m = fmaxf(m, fabsf(W[(size_t)k * NW + n]));
    g_gw[z * NW + n] = (m + 1e-30f) / 16256.f;
}

// ---------------------------------------------------------------------------
// Prep: transpose W [K,N] -> [N,K] and split to int8 hi/lo
// ---------------------------------------------------------------------------
__global__ __launch_bounds__(256) void prep_w_i8(
    const float* __restrict__ Wq, const float* __restrict__ Wk,
    const float* __restrict__ Wv)
{
    const int z = blockIdx.z;
    const float* W = (z == 0) ? Wq : ((z == 1) ? Wk : Wv);
    const int n0 = blockIdx.x * 32;
    const int k0 = blockIdx.y * 32;

    __shared__ float t[32][33];
    const int tx = threadIdx.x, ty = threadIdx.y;
#pragma unroll
    for (int j = 0; j < 4; j++)
        t[ty + 8 * j][tx] = W[(size_t)(k0 + ty + 8 * j) * NW + n0 + tx];
    __syncthreads();
#pragma unroll
    for (int j = 0; j < 4; j++) {
        const int n = n0 + ty + 8 * j;
        const float S = 1.f / g_gw[z * NW + n];
        float v = t[tx][ty + 8 * j];
        int8_t h, l;
        split15(v, S, h, l);
        size_t o = ((size_t)z * NW + n) * CDIM + k0 + tx;
        g_W1[o] = h;
        g_W0[o] = l;
    }
}

// ---------------------------------------------------------------------------
// Projection via int8 mma (m16n8k32), 3-term 15-bit fixed point, fused
// RoPE+SiLU epilogue, output hi/lo bf16.
// CTA tile M=128, N=128, K-stage 32, 3-stage pipe, 8 warps (2m x 4n),
// warp tile 64x32.  smem rows stride 48B (conflict-free for t4*4 pattern).
// stage: A1@0 A0@6144 B1@12288 B0@18432; stage 24576 B.
// ---------------------------------------------------------------------------
#define ISTAGE 24576
#define SMEM_PI (3 * ISTAGE)

__device__ __forceinline__ void proj_i8_load(
    uint32_t stb, int tid, int m0, int zn0, int k0)
{
#pragma unroll
    for (int i = 0; i < 4; i++) {
        const int c = tid + i * 256;
        const int mat  = (c >> 8) & 1;
        const int rem  = c & 255;
        const int row  = rem >> 1;
        const int half = rem & 1;
        if (c < 512) {
            const int8_t* src = (mat ? g_X0 : g_X1)
                + (size_t)(m0 + row) * CDIM + k0 + half * 16;
            CP16(stb + mat * 6144 + row * 48 + half * 16, src);
        } else {
            const int8_t* src = (mat ? g_W0 : g_W1)
                + (size_t)(zn0 + row) * CDIM + k0 + half * 16;
            CP16(stb + 12288 + mat * 6144 + row * 48 + half * 16, src);
        }
    }
}

__global__ __launch_bounds__(256, 1) void proj_i8()
{
    extern __shared__ char smem[];
    const uint32_t sb = smem_u32(smem);
    const int tid = threadIdx.x;
    const int wid = tid >> 5;
    const int lane = tid & 31;
    const int wm = wid & 1, wn = wid >> 1;
    const int g = lane >> 2, t4 = lane & 3;

    const int m0 = blockIdx.x * 128;
    const int n0 = blockIdx.y * 128;
    const int z  = blockIdx.z;
    const int zn0 = z * NW + n0;

    int acch[4][4][4], accc[4][4][4];
#pragma unroll
    for (int i = 0; i < 4; i++)
#pragma unroll
        for (int j = 0; j < 4; j++)
#pragma unroll
            for (int q = 0; q < 4; q++) { acch[i][j][q] = 0; accc[i][j][q] = 0; }

    proj_i8_load(sb, tid, m0, zn0, 0);
    CP_COMMIT();
    proj_i8_load(sb + ISTAGE, tid, m0, zn0, 32);
    CP_COMMIT();

#pragma unroll 1
    for (int s = 0; s < 32; s++) {
        if (s < 31) { CP_WAIT1(); } else { CP_WAIT0(); }
        __syncthreads();
        if (s + 2 < 32) {
            proj_i8_load(sb + ((s + 2) % 3) * ISTAGE, tid, m0, zn0, (s + 2) * 32);
            CP_COMMIT();
        }
        const char* st = smem + (s % 3) * ISTAGE;
        const char* A1 = st;
        const char* A0 = st + 6144;
        const char* B1 = st + 12288;
        const char* B0 = st + 18432;

        uint32_t a1[4][4], a0[4][4];
#pragma unroll
        for (int i = 0; i < 4; i++) {
            const int b = (wm * 64 + i * 16 + g) * 48 + t4 * 4;
            a1[i][0] = *(const uint32_t*)(A1 + b);
            a1[i][1] = *(const uint32_t*)(A1 + b + 384);
            a1[i][2] = *(const uint32_t*)(A1 + b + 16);
            a1[i][3] = *(const uint32_t*)(A1 + b + 400);
            a0[i][0] = *(const uint32_t*)(A0 + b);
            a0[i][1] = *(const uint32_t*)(A0 + b + 384);
            a0[i][2] = *(const uint32_t*)(A0 + b + 16);
            a0[i][3] = *(const uint32_t*)(A0 + b + 400);
        }
        uint32_t b1[4][2], b0[4][2];
#pragma unroll
        for (int j = 0; j < 4; j++) {
            const int b = (wn * 32 + j * 8 + g) * 48 + t4 * 4;
            b1[j][0] = *(const uint32_t*)(B1 + b);
            b1[j][1] = *(const uint32_t*)(B1 + b + 16);
            b0[j][0] = *(const uint32_t*)(B0 + b);
            b0[j][1] = *(const uint32_t*)(B0 + b + 16);
        }
#pragma unroll
        for (int i = 0; i < 4; i++)
#pragma unroll
            for (int j = 0; j < 4; j++) {
                mma_s8(acch[i][j], a1[i], b1[j]);
                mma_s8(accc[i][j], a1[i], b0[j]);
                mma_s8(accc[i][j], a0[i], b1[j]);
            }
    }

    // epilogue: dequant + RoPE (cols<64 of Q,K) + SiLU + bf16 hi/lo store
    __nv_bfloat16* Hi = (z == 0) ? g_Qhi : ((z == 1) ? g_Khi : g_Vhi);
    __nv_bfloat16* Lo = (z == 0) ? g_Qlo : ((z == 1) ? g_Klo : g_Vlo);

#pragma unroll
    for (int i = 0; i < 4; i++) {
#pragma unroll
        for (int rr = 0; rr < 2; rr++) {
            const int r = m0 + wm * 64 + i * 16 + g + rr * 8;
            const float gx = g_sx[r];
#pragma unroll
            for (int j = 0; j < 4; j++) {
                const int nn = n0 + wn * 32 + j * 8 + 2 * t4;
                const int h = nn >> 10, c = nn & 1023;
                const float gw0 = g_gw[z * NW + nn];
                const float gw1 = g_gw[z * NW + nn + 1];
                float v0 = ((float)acch[i][j][2 * rr] * 16384.f +
                            (float)accc[i][j][2 * rr] * 128.f) * gx * gw0;
                float v1 = ((float)acch[i][j][2 * rr + 1] * 16384.f +
                            (float)accc[i][j][2 * rr + 1] * 128.f) * gx * gw1;
                if (z < 2 && c < 64) {
                    float invf = (float)exp(-((double)c / 64.0) * log(10000.0));
                    float ang = (float)r * invf;
                    float sn, cs;
                    sincosf(ang, &sn, &cs);
                    float y0 = v0 * cs - v1 * sn;
                    float y1 = v1 * cs + v0 * sn;
                    v0 = y0; v1 = y1;
                }
                v0 = v0 / (1.f + expf(-v0));
                v1 = v1 / (1.f + expf(-v1));
                uint32_t lo, hi = pack_bf2(v0, v1, lo);
                size_t idx = (((size_t)h * TDIM + r) * CDIM + c) >> 1;
                ((uint32_t*)Hi)[idx] = hi;
                ((uint32_t*)Lo)[idx] = lo;
            }
        }
    }
}

// ---------------------------------------------------------------------------
// V transpose: [h][t][c] -> [h][c][t] (hi & lo)
// ---------------------------------------------------------------------------
__global__ void transpose_v()
{
    __shared__ unsigned short sh[32][33], sl[32][33];
    const int c0 = blockIdx.x * 32;
    const int t0 = blockIdx.y * 32;
    const int h  = blockIdx.z;
    const int tx = threadIdx.x, ty = threadIdx.y;

    const unsigned short* Vh = (const unsigned short*)g_Vhi + (size_t)h * TDIM * CDIM;
    const unsigned short* Vl = (const unsigned short*)g_Vlo + (size_t)h * TDIM * CDIM;
#pragma unroll
    for (int k = 0; k < 4; k++) {
        int r = ty + 8 * k;
        sh[r][tx] = Vh[(size_t)(t0 + r) * CDIM + c0 + tx];
        sl[r][tx] = Vl[(size_t)(t0 + r) * CDIM + c0 + tx];
    }
    __syncthreads();
    unsigned short* Th = (unsigned short*)g_Vthi + (size_t)h * CDIM * TDIM;
    unsigned short* Tl = (unsigned short*)g_Vtlo + (size_t)h * CDIM * TDIM;
#pragma unroll
    for (int k = 0; k < 4; k++) {
        int r = ty + 8 * k;
        Th[(size_t)(c0 + r) * TDIM + t0 + tx] = sh[tx][r];
        Tl[(size_t)(c0 + r) * TDIM + t0 + tx] = sl[tx][r];
    }
}

// ---------------------------------------------------------------------------
// qk_mma: banded scores P = decay * (K Q^T), bf16 split, M=64(t) N=256(q) K=1024
// ---------------------------------------------------------------------------
#define QKSTAGE 51200
#define SMEM_QK (3 * QKSTAGE)

__global__ __launch_bounds__(256, 1) void qk_mma()
{
    extern __shared__ char smem[];
    const uint32_t sb = smem_u32(smem);
    const int tid = threadIdx.x;
    const int wid = tid >> 5;
    const int lane = tid & 31;
    const int wm = wid & 1, wn = wid >> 1;
    const int g = lane >> 2, t4 = lane & 3;

    const int qc   = blockIdx.x;          // 0..1
    const int tile = blockIdx.y;
    const int h    = blockIdx.z;
    const int t0   = tile * TT;
    const int q0   = t0 + qc * 256;

    const __nv_bfloat16* Kh = g_Khi + (size_t)h * TDIM * CDIM;
    const __nv_bfloat16* Kl = g_Klo + (size_t)h * TDIM * CDIM;
    const __nv_bfloat16* Qh = g_Qhi + (size_t)h * TDIM * CDIM;
    const __nv_bfloat16* Ql = g_Qlo + (size_t)h * TDIM * CDIM;

    float acc[2][8][4];
#pragma unroll
    for (int i = 0; i < 2; i++)
#pragma unroll
        for (int j = 0; j < 8; j++)
#pragma unroll
            for (int q = 0; q < 4; q++) acc[i][j][q] = 0.f;

    auto load_stage = [&](int s, uint32_t stb) {
        const int k0 = s * 32;
#pragma unroll
        for (int i = 0; i < 10; i++) {
            const int c = tid + i * 256;
            if (c < 512) {
                const int mat = c >> 8, rem = c & 255;
                const int row = rem >> 2, ch = rem & 3;
                const __nv_bfloat16* src = (mat ? Kl : Kh)
                    + (size_t)(t0 + row) * CDIM + k0 + ch * 8;
                CP16(stb + mat * 5120 + row * 80 + ch * 16, src);
            } else {
                const int cb = c - 512;
                const int mat = cb >> 10, rem = cb & 1023;
                const int row = rem >> 2, ch = rem & 3;
                int q = q0 + row;
                int sz = (q < TDIM) ? 16 : 0;
                if (q >= TDIM) q = 0;
                const __nv_bfloat16* src = (mat ? Ql : Qh)
                    + (size_t)q * CDIM + k0 + ch * 8;
                CP16Z(stb + 10240 + mat * 20480 + row * 80 + ch * 16, src, sz);
            }
        }
    };

    load_stage(0, sb);
    CP_COMMIT();
    load_stage(1, sb + QKSTAGE);
    CP_COMMIT();

#pragma unroll 1
    for (int s = 0; s < 32; s++) {
        if (s < 31) { CP_WAIT1(); } else { CP_WAIT0(); }
        __syncthreads();
        if (s + 2 < 32) {
            load_stage(s + 2, sb + ((s + 2) % 3) * QKSTAGE);
            CP_COMMIT();
        }
        const char* st = smem + (s % 3) * QKSTAGE;

        const char* Ah = st;
        const char* Al = st + 5120;
        const char* Bh = st + 10240;
        const char* Bl = st + 30720;

#pragma unroll
        for (int kk = 0; kk < 32; kk += 16) {
            uint32_t ah[2][4], al[2][4];
#pragma unroll
            for (int i = 0; i < 2; i++) {
                const int b0 = (wm * 32 + i * 16 + g) * 80 + kk * 2 + t4 * 4;
                ah[i][0] = *(const uint32_t*)(Ah + b0);
                ah[i][1] = *(const uint32_t*)(Ah + b0 + 640);
                ah[i][2] = *(const uint32_t*)(Ah + b0 + 16);
                ah[i][3] = *(const uint32_t*)(Ah + b0 + 656);
                al[i][0] = *(const uint32_t*)(Al + b0);
                al[i][1] = *(const uint32_t*)(Al + b0 + 640);
                al[i][2] = *(const uint32_t*)(Al + b0 + 16);
                al[i][3] = *(const uint32_t*)(Al + b0 + 656);
            }
#pragma unroll
            for (int jj = 0; jj < 2; jj++) {
                uint32_t bh[4][2], bl[4][2];
#pragma unroll
                for (int j = 0; j < 4; j++) {
                    const int bb = (wn * 64 + jj * 32 + j * 8 + g) * 80 + kk * 2 + t4 * 4;
                    bh[j][0] = *(const uint32_t*)(Bh + bb);
                    bh[j][1] = *(const uint32_t*)(Bh + bb + 16);
                    bl[j][0] = *(const uint32_t*)(Bl + bb);
                    bl[j][1] = *(const uint32_t*)(Bl + bb + 16);
                }
#pragma unroll
                for (int i = 0; i < 2; i++)
#pragma unroll
                    for (int j = 0; j < 4; j++) {
                        float* c = acc[i][jj * 4 + j];
                        mma_bf16(c, ah[i], bh[j]);
                        mma_bf16(c, ah[i], bl[j]);
                        mma_bf16(c, al[i], bh[j]);
                    }
            }
        }
    }

    // epilogue: decay + mask, split hi/lo, store P
    const float lg = log2f(GAMMA);
    __nv_bfloat16* Phb = g_Phi + ((size_t)h * NTIL + tile) * TT * KQ;
    __nv_bfloat16* Plb = g_Plo + ((size_t)h * NTIL + tile) * TT * KQ;
#pragma unroll
    for (int i = 0; i < 2; i++) {
#pragma unroll
        for (int rr = 0; rr < 2; rr++) {
            const int tl = wm * 32 + i * 16 + g + rr * 8;
            const int t  = t0 + tl;
#pragma unroll
            for (int j = 0; j < 8; j++) {
                const int ql = qc * 256 + wn * 64 + j * 8 + 2 * t4;
                const int q  = t0 + ql;
                float v0 = acc[i][j][2 * rr];
                float v1 = acc[i][j][2 * rr + 1];
                int wd0 = q - t, wd1 = wd0 + 1;
                v0 = (wd0 >= 0 && wd0 < WIN && q < TDIM)
                     ? v0 * exp2f((float)wd0 * lg) : 0.f;
                v1 = (wd1 >= 0 && wd1 < WIN && (q + 1) < TDIM)
                     ? v1 * exp2f((float)wd1 * lg) : 0.f;
                uint32_t lo, hi = pack_bf2(v0, v1, lo);
                size_t idx = ((size_t)tl * KQ + ql) >> 1;
                ((uint32_t*)Phb)[idx] = hi;
                ((uint32_t*)Plb)[idx] = lo;
            }
        }
    }
}

// ---------------------------------------------------------------------------
// av_mma: out[t][c] = sum_{h,q} P[h,tile,t,q] * V[h, t0+q, c]
// M=64(t) N=256(c) K=4096
// ---------------------------------------------------------------------------
#define AVSTAGE 51200
#define SMEM_AV (3 * AVSTAGE)

__global__ __launch_bounds__(256, 1) void av_mma(float* __restrict__ out)
{
    extern __shared__ char smem[];
    const uint32_t sb = smem_u32(smem);
    const int tid = threadIdx.x;
    const int wid = tid >> 5;
    const int lane = tid & 31;
    const int wm = wid & 1, wn = wid >> 1;
    const int g = lane >> 2, t4 = lane & 3;

    const int cc   = blockIdx.x;      // 0..3
    const int tile = blockIdx.y;
    const int t0   = tile * TT;
    const int c0   = cc * 256;

    float acc[2][8][4];
#pragma unroll
    for (int i = 0; i < 2; i++)
#pragma unroll
        for (int j = 0; j < 8; j++)
#pragma unroll
            for (int q = 0; q < 4; q++) acc[i][j][q] = 0.f;

    auto load_stage = [&](int s, uint32_t stb) {
        const int kk0 = s * 32;
        const int h   = kk0 >> 9;
        const int ql  = kk0 & 511;
#pragma unroll
        for (int i = 0; i < 10; i++) {
            const int c = tid + i * 256;
            if (c < 512) {
                const int mat = c >> 8, rem = c & 255;
                const int row = rem >> 2, ch = rem & 3;
                const __nv_bfloat16* src = (mat ? g_Plo : g_Phi)
                    + ((size_t)h * NTIL + tile) * TT * KQ
                    + (size_t)row * KQ + ql + ch * 8;
                CP16(stb + mat * 5120 + row * 80 + ch * 16, src);
            } else {
                const int cb = c - 512;
                const int mat = cb >> 10, rem = cb & 1023;
                const int row = rem >> 2, ch = rem & 3;
                int tg = t0 + ql + ch * 8;
                int sz = (tg < TDIM) ? 16 : 0;
                if (tg >= TDIM) tg = 0;
                const __nv_bfloat16* src = (mat ? g_Vtlo : g_Vthi)
                    + ((size_t)h * CDIM + c0 + row) * TDIM + tg;
                CP16Z(stb + 10240 + mat * 20480 + row * 80 + ch * 16, src, sz);
            }
        }
    };

    load_stage(0, sb);
    CP_COMMIT();
    load_stage(1, sb + AVSTAGE);
    CP_COMMIT();

#pragma unroll 1
    for (int s = 0; s < 128; s++) {
        if (s < 127) { CP_WAIT1(); } else { CP_WAIT0(); }
        __syncthreads();
        if (s + 2 < 128) {
            load_stage(s + 2, sb + ((s + 2) % 3) * AVSTAGE);
            CP_COMMIT();
        }
        const char* st = smem + (s % 3) * AVSTAGE;

        const char* Ah = st;
        const char* Al = st + 5120;
        const char* Bh = st + 10240;
        const char* Bl = st + 30720;

#pragma unroll
        for (int kk = 0; kk < 32; kk += 16) {
            uint32_t ah[2][4], al[2][4];
#pragma unroll
            for (int i = 0; i < 2; i++) {
                const int b0 = (wm * 32 + i * 16 + g) * 80 + kk * 2 + t4 * 4;
                ah[i][0] = *(const uint32_t*)(Ah + b0);
                ah[i][1] = *(const uint32_t*)(Ah + b0 + 640);
                ah[i][2] = *(const uint32_t*)(Ah + b0 + 16);
                ah[i][3] = *(const uint32_t*)(Ah + b0 + 656);
                al[i][0] = *(const uint32_t*)(Al + b0);
                al[i][1] = *(const uint32_t*)(Al + b0 + 640);
                al[i][2] = *(const uint32_t*)(Al + b0 + 16);
                al[i][3] = *(const uint32_t*)(Al + b0 + 656);
            }
#pragma unroll
            for (int jj = 0; jj < 2; jj++) {
                uint32_t bh[4][2], bl[4][2];
#pragma unroll
                for (int j = 0; j < 4; j++) {
                    const int bb = (wn * 64 + jj * 32 + j * 8 + g) * 80 + kk * 2 + t4 * 4;
                    bh[j][0] = *(const uint32_t*)(Bh + bb);
                    bh[j][1] = *(const uint32_t*)(Bh + bb + 16);
                    bl[j][0] = *(const uint32_t*)(Bl + bb);
                    bl[j][1] = *(const uint32_t*)(Bl + bb + 16);
                }
#pragma unroll
                for (int i = 0; i < 2; i++)
#pragma unroll
                    for (int j = 0; j < 4; j++) {
                        float* c = acc[i][jj * 4 + j];
                        mma_bf16(c, ah[i], bh[j]);
                        mma_bf16(c, ah[i], bl[j]);
                        mma_bf16(c, al[i], bh[j]);
                    }
            }
        }
    }

    // epilogue: fp32 out
#pragma unroll
    for (int i = 0; i < 2; i++) {
#pragma unroll
        for (int rr = 0; rr < 2; rr++) {
            const int t = t0 + wm * 32 + i * 16 + g + rr * 8;
#pragma unroll
            for (int j = 0; j < 8; j++) {
                const int c = c0 + wn * 64 + j * 8 + 2 * t4;
                *(float2*)(out + (size_t)t * CDIM + c) =
                    make_float2(acc[i][j][2 * rr], acc[i][j][2 * rr + 1]);
            }
        }
    }
}

// ---------------------------------------------------------------------------
// GroupNorm in place on out
// ---------------------------------------------------------------------------
__global__ __launch_bounds__(256) void gn_kernel(
    float* __restrict__ out,
    const float* __restrict__ wgt,
    const float* __restrict__ bias)
{
    const int t = blockIdx.x;
    const int tid = threadIdx.x;

    float4 v = *(float4*)(out + (size_t)t * CDIM + tid * 4);
    float s  = v.x + v.y + v.z + v.w;
    float sq = v.x * v.x + v.y * v.y + v.z * v.z + v.w * v.w;

#pragma unroll
    for (int off = 8; off > 0; off >>= 1) {
        s  += __shfl_down_sync(0xffffffffu, s,  off, 16);
        sq += __shfl_down_sync(0xffffffffu, sq, off, 16);
    }
    s  = __shfl_sync(0xffffffffu, s,  0, 16);
    sq = __shfl_sync(0xffffffffu, sq, 0, 16);

    float mean = s * (1.f / 64.f);
    float var  = sq * (1.f / 64.f) - mean * mean;
    float rs   = rsqrtf(var + 1e-5f);

    float4 w4 = *(const float4*)(wgt + tid * 4);
    float4 b4 = *(const float4*)(bias + tid * 4);
    v.x = (v.x - mean) * rs * w4.x + b4.x;
    v.y = (v.y - mean) * rs * w4.y + b4.y;
    v.z = (v.z - mean) * rs * w4.z + b4.z;
    v.w = (v.w - mean) * rs * w4.w + b4.w;
    *(float4*)(out + (size_t)t * CDIM + tid * 4) = v;
}

// ---------------------------------------------------------------------------
extern "C" void kernel_launch(void* const* d_in, const int* in_sizes, int n_in,
                              void* d_out, int out_size)
{
    const float* X  = (const float*)d_in[0];
    const float* Wq = (const float*)d_in[1];
    const float* Wk = (const float*)d_in[2];
    const float* Wv = (const float*)d_in[3];
    const float* gw = (const float*)d_in[4];
    const float* gb = (const float*)d_in[5];
    float* out = (float*)d_out;

    prep_x_i8<<<TDIM, 256>>>(X);
    prep_wmax<<<dim3(NW / 256, 3), 256>>>(Wq, Wk, Wv);
    prep_w_i8<<<dim3(NW / 32, CDIM / 32, 3), dim3(32, 8)>>>(Wq, Wk, Wv);

    cudaFuncSetAttribute(proj_i8, cudaFuncAttributeMaxDynamicSharedMemorySize,
                         SMEM_PI);
    proj_i8<<<dim3(16, 64, 3), 256, SMEM_PI>>>();

    transpose_v<<<dim3(CDIM / 32, TDIM / 32, HN), dim3(32, 8)>>>();

    cudaFuncSetAttribute(qk_mma, cudaFuncAttributeMaxDynamicSharedMemorySize,
                         SMEM_QK);
    qk_mma<<<dim3(2, NTIL, HN), 256, SMEM_QK>>>();

    cudaFuncSetAttribute(av_mma, cudaFuncAttributeMaxDynamicSharedMemorySize,
                         SMEM_AV);
    av_mma<<<dim3(4, NTIL), 256, SMEM_AV>>>(out);

    gn_kernel<<<TDIM, 256>>>(out, gw, gb);
}

// round 7
// speedup vs baseline: 2.2839x; 2.2839x over previous
#include <cuda_runtime.h>
#include <cuda_fp16.h>
#include <math.h>
#include <stdint.h>

#define TDIM 2048
#define CDIM 1024
#define HN   8
#define NW   8192
#define WIN  448
#define KQ   512
#define TT   64
#define NTIL 32
#define GAMMA 0.96875f

// fp16 operands.  A-sides split (hi+lo exact), B-sides single fp16.
__device__ __half g_Xh[(size_t)TDIM * CDIM];
__device__ __half g_Xl[(size_t)TDIM * CDIM];
__device__ __half g_Wth[(size_t)3 * NW * CDIM];            // [z][n][k] single
__device__ __half g_Qh[(size_t)HN * TDIM * CDIM];          // single (B of qk)
__device__ __half g_Kh[(size_t)HN * TDIM * CDIM];          // split (A of qk)
__device__ __half g_Kl[(size_t)HN * TDIM * CDIM];
__device__ __half g_Vh[(size_t)HN * TDIM * CDIM];          // [h][t][c] single
__device__ __half g_Vth[(size_t)HN * CDIM * TDIM];         // [h][c][t] single
__device__ __half g_Ph[(size_t)HN * NTIL * TT * KQ];       // split (A of av)
__device__ __half g_Pl[(size_t)HN * NTIL * TT * KQ];

// ---------------------------------------------------------------------------
#define CP16(dst, src) \
    asm volatile("cp.async.cg.shared.global [%0], [%1], 16;" :: "r"(dst), "l"(src))
#define CP16Z(dst, src, sz) \
    asm volatile("cp.async.cg.shared.global [%0], [%1], 16, %2;" :: "r"(dst), "l"(src), "r"(sz))
#define CP_COMMIT() asm volatile("cp.async.commit_group;" ::: "memory")
#define CP_WAIT1()  asm volatile("cp.async.wait_group 1;" ::: "memory")
#define CP_WAIT0()  asm volatile("cp.async.wait_group 0;" ::: "memory")

__device__ __forceinline__ uint32_t smem_u32(const void* p) {
    uint32_t a;
    asm("{ .reg .u64 t; cvta.to.shared.u64 t, %1; cvt.u32.u64 %0, t; }"
        : "=r"(a) : "l"(p));
    return a;
}

__device__ __forceinline__ void mma_f16(float c[4], const uint32_t a[4],
                                        const uint32_t b[2]) {
    asm volatile(
        "mma.sync.aligned.m16n8k16.row.col.f32.f16.f16.f32 "
        "{%0,%1,%2,%3}, {%4,%5,%6,%7}, {%8,%9}, {%0,%1,%2,%3};"
        : "+f"(c[0]), "+f"(c[1]), "+f"(c[2]), "+f"(c[3])
        : "r"(a[0]), "r"(a[1]), "r"(a[2]), "r"(a[3]), "r"(b[0]), "r"(b[1]));
}

__device__ __forceinline__ uint32_t pack_h2(float v0, float v1) {
    __half2 h = __floats2half2_rn(v0, v1);
    return *(uint32_t*)&h;
}
__device__ __forceinline__ uint32_t pack_h2_split(float v0, float v1, uint32_t& lo) {
    __half h0 = __float2half_rn(v0), h1 = __float2half_rn(v1);
    __half l0 = __float2half_rn(v0 - __half2float(h0));
    __half l1 = __float2half_rn(v1 - __half2float(h1));
    lo = (uint32_t)*(unsigned short*)&l0 | ((uint32_t)*(unsigned short*)&l1 << 16);
    return (uint32_t)*(unsigned short*)&h0 | ((uint32_t)*(unsigned short*)&h1 << 16);
}

// ---------------------------------------------------------------------------
// Prep: split X into hi/lo fp16
// ---------------------------------------------------------------------------
__global__ __launch_bounds__(256) void prep_x(const float* __restrict__ X)
{
    int i = blockIdx.x * 256 + threadIdx.x;
    float4 v = ((const float4*)X)[i];
    uint32_t l0, l1;
    uint32_t h0 = pack_h2_split(v.x, v.y, l0);
    uint32_t h1 = pack_h2_split(v.z, v.w, l1);
    ((uint2*)g_Xh)[i] = make_uint2(h0, h1);
    ((uint2*)g_Xl)[i] = make_uint2(l0, l1);
}

// ---------------------------------------------------------------------------
// Prep: transpose W [K,N] -> Wt [N,K], single fp16
// ---------------------------------------------------------------------------
__global__ __launch_bounds__(256) void prep_w(
    const float* __restrict__ Wq, const float* __restrict__ Wk,
    const float* __restrict__ Wv)
{
    const int z = blockIdx.z;
    const float* W = (z == 0) ? Wq : ((z == 1) ? Wk : Wv);
    const int n0 = blockIdx.x * 32;
    const int k0 = blockIdx.y * 32;

    __shared__ float t[32][33];
    const int tx = threadIdx.x, ty = threadIdx.y;
#pragma unroll
    for (int j = 0; j < 4; j++)
        t[ty + 8 * j][tx] = W[(size_t)(k0 + ty + 8 * j) * NW + n0 + tx];
    __syncthreads();
#pragma unroll
    for (int j = 0; j < 4; j++) {
        float v = t[tx][ty + 8 * j];
        size_t o = ((size_t)z * NW + n0 + ty + 8 * j) * CDIM + k0 + tx;
        g_Wth[o] = __float2half_rn(v);
    }
}

// ---------------------------------------------------------------------------
// Projection: 2-term fp16 split (X hi/lo x W single), fused RoPE+SiLU,
// outputs: Q hi, K hi+lo, V hi.  CTA tile M=128 N=256 Kstage=32, 3-stage.
// stage: Ah[128][80B]@0 (10240) | Al@10240 | Bh[256][80B]@20480 (20480)
// ---------------------------------------------------------------------------
#define PSTAGE 40960
#define SMEM_PROJ (3 * PSTAGE)

__device__ __forceinline__ void proj_load_stage(
    uint32_t stb, int tid, int m0, int zn0, int k0)
{
#pragma unroll
    for (int i = 0; i < 8; i++) {
        const int c = tid + i * 256;
        if (c < 1024) {
            const int mat = c >> 9;
            const int rem = c & 511;
            const int row = rem >> 2;
            const int ch  = rem & 3;
            const __half* src = (mat ? g_Xl : g_Xh)
                + (size_t)(m0 + row) * CDIM + k0 + ch * 8;
            CP16(stb + mat * 10240 + row * 80 + ch * 16, src);
        } else {
            const int rem = c - 1024;
            const int row = rem >> 2;
            const int ch  = rem & 3;
            const __half* src = g_Wth + (size_t)(zn0 + row) * CDIM + k0 + ch * 8;
            CP16(stb + 20480 + row * 80 + ch * 16, src);
        }
    }
}

__global__ __launch_bounds__(256, 1) void proj_mma()
{
    extern __shared__ char smem[];
    const uint32_t sb = smem_u32(smem);
    const int tid = threadIdx.x;
    const int wid = tid >> 5;
    const int lane = tid & 31;
    const int wm = wid & 1, wn = wid >> 1;
    const int g = lane >> 2, t4 = lane & 3;

    const int m0 = blockIdx.x * 128;
    const int n0 = blockIdx.y * 256;
    const int z  = blockIdx.z;
    const int zn0 = z * NW + n0;

    float acc[4][8][4];
#pragma unroll
    for (int i = 0; i < 4; i++)
#pragma unroll
        for (int j = 0; j < 8; j++)
#pragma unroll
            for (int q = 0; q < 4; q++) acc[i][j][q] = 0.f;

    proj_load_stage(sb, tid, m0, zn0, 0);
    CP_COMMIT();
    proj_load_stage(sb + PSTAGE, tid, m0, zn0, 32);
    CP_COMMIT();

#pragma unroll 1
    for (int s = 0; s < 32; s++) {
        if (s < 31) { CP_WAIT1(); } else { CP_WAIT0(); }
        __syncthreads();
        if (s + 2 < 32) {
            proj_load_stage(sb + ((s + 2) % 3) * PSTAGE, tid, m0, zn0, (s + 2) * 32);
            CP_COMMIT();
        }
        const char* st = smem + (s % 3) * PSTAGE;
        const char* Ah = st;
        const char* Al = st + 10240;
        const char* Bh = st + 20480;

#pragma unroll
        for (int kk = 0; kk < 32; kk += 16) {
            uint32_t ah[4][4], al[4][4];
#pragma unroll
            for (int i = 0; i < 4; i++) {
                const int b0 = (wm * 64 + i * 16 + g) * 80 + kk * 2 + t4 * 4;
                ah[i][0] = *(const uint32_t*)(Ah + b0);
                ah[i][1] = *(const uint32_t*)(Ah + b0 + 640);
                ah[i][2] = *(const uint32_t*)(Ah + b0 + 16);
                ah[i][3] = *(const uint32_t*)(Ah + b0 + 656);
                al[i][0] = *(const uint32_t*)(Al + b0);
                al[i][1] = *(const uint32_t*)(Al + b0 + 640);
                al[i][2] = *(const uint32_t*)(Al + b0 + 16);
                al[i][3] = *(const uint32_t*)(Al + b0 + 656);
            }
#pragma unroll
            for (int jj = 0; jj < 2; jj++) {
                uint32_t bh[4][2];
#pragma unroll
                for (int j = 0; j < 4; j++) {
                    const int bb = (wn * 64 + jj * 32 + j * 8 + g) * 80 + kk * 2 + t4 * 4;
                    bh[j][0] = *(const uint32_t*)(Bh + bb);
                    bh[j][1] = *(const uint32_t*)(Bh + bb + 16);
                }
#pragma unroll
                for (int i = 0; i < 4; i++)
#pragma unroll
                    for (int j = 0; j < 4; j++) {
                        float* c = acc[i][jj * 4 + j];
                        mma_f16(c, ah[i], bh[j]);
                        mma_f16(c, al[i], bh[j]);
                    }
            }
        }
    }

    // epilogue: RoPE (Q,K cols<64) + SiLU, fp16 store (lo only for K)
    const int h  = n0 >> 10;
    const int cbase = (n0 & 1023) + wn * 64 + 2 * t4;
    const bool rope_blk = (z < 2) && ((n0 & 1023) == 0) && (wn == 0);

    __half* Hi = (z == 0) ? g_Qh : ((z == 1) ? g_Kh : g_Vh);
    Hi += (size_t)h * TDIM * CDIM;
    __half* Lo = g_Kl + (size_t)h * TDIM * CDIM;

#pragma unroll
    for (int i = 0; i < 4; i++) {
#pragma unroll
        for (int rr = 0; rr < 2; rr++) {
            const int r = m0 + wm * 64 + i * 16 + g + rr * 8;
#pragma unroll
            for (int j = 0; j < 8; j++) {
                const int col = cbase + j * 8;
                float v0 = acc[i][j][2 * rr];
                float v1 = acc[i][j][2 * rr + 1];
                if (rope_blk) {
                    int c2 = col >> 1;
                    float invf = (float)exp(-((double)(2 * c2) / 64.0) * log(10000.0));
                    float ang = (float)r * invf;
                    float sn, cs;
                    sincosf(ang, &sn, &cs);
                    float y0 = v0 * cs - v1 * sn;
                    float y1 = v1 * cs + v0 * sn;
                    v0 = y0; v1 = y1;
                }
                v0 = v0 / (1.f + expf(-v0));
                v1 = v1 / (1.f + expf(-v1));
                size_t idx = ((size_t)r * CDIM + col) >> 1;
                if (z == 1) {
                    uint32_t lo, hi = pack_h2_split(v0, v1, lo);
                    ((uint32_t*)Hi)[idx] = hi;
                    ((uint32_t*)Lo)[idx] = lo;
                } else {
                    ((uint32_t*)Hi)[idx] = pack_h2(v0, v1);
                }
            }
        }
    }
}

// ---------------------------------------------------------------------------
// V transpose: [h][t][c] -> [h][c][t] (hi only)
// ---------------------------------------------------------------------------
__global__ void transpose_v()
{
    __shared__ unsigned short sh[32][33];
    const int c0 = blockIdx.x * 32;
    const int t0 = blockIdx.y * 32;
    const int h  = blockIdx.z;
    const int tx = threadIdx.x, ty = threadIdx.y;

    const unsigned short* Vh = (const unsigned short*)g_Vh + (size_t)h * TDIM * CDIM;
#pragma unroll
    for (int k = 0; k < 4; k++) {
        int r = ty + 8 * k;
        sh[r][tx] = Vh[(size_t)(t0 + r) * CDIM + c0 + tx];
    }
    __syncthreads();
    unsigned short* Th = (unsigned short*)g_Vth + (size_t)h * CDIM * TDIM;
#pragma unroll
    for (int k = 0; k < 4; k++) {
        int r = ty + 8 * k;
        Th[(size_t)(c0 + r) * TDIM + t0 + tx] = sh[tx][r];
    }
}

// ---------------------------------------------------------------------------
// qk_mma: P = decay * (K Q^T).  A = K hi/lo (split), B = Q hi (single).
// M=64(t) N=256(q) K=1024. stage: Ah@0(5120) Al@5120 Bq@10240(20480)
// ---------------------------------------------------------------------------
#define QKSTAGE 30720
#define SMEM_QK (3 * QKSTAGE)

__global__ __launch_bounds__(256, 1) void qk_mma()
{
    extern __shared__ char smem[];
    const uint32_t sb = smem_u32(smem);
    const int tid = threadIdx.x;
    const int wid = tid >> 5;
    const int lane = tid & 31;
    const int wm = wid & 1, wn = wid >> 1;
    const int g = lane >> 2, t4 = lane & 3;

    const int qc   = blockIdx.x;          // 0..1
    const int tile = blockIdx.y;
    const int h    = blockIdx.z;
    const int t0   = tile * TT;
    const int q0   = t0 + qc * 256;

    const __half* Kh = g_Kh + (size_t)h * TDIM * CDIM;
    const __half* Kl = g_Kl + (size_t)h * TDIM * CDIM;
    const __half* Qh = g_Qh + (size_t)h * TDIM * CDIM;

    float acc[2][8][4];
#pragma unroll
    for (int i = 0; i < 2; i++)
#pragma unroll
        for (int j = 0; j < 8; j++)
#pragma unroll
            for (int q = 0; q < 4; q++) acc[i][j][q] = 0.f;

    auto load_stage = [&](int s, uint32_t stb) {
        const int k0 = s * 32;
#pragma unroll
        for (int i = 0; i < 6; i++) {
            const int c = tid + i * 256;
            if (c < 512) {
                const int mat = c >> 8, rem = c & 255;
                const int row = rem >> 2, ch = rem & 3;
                const __half* src = (mat ? Kl : Kh)
                    + (size_t)(t0 + row) * CDIM + k0 + ch * 8;
                CP16(stb + mat * 5120 + row * 80 + ch * 16, src);
            } else {
                const int rem = c - 512;                 // 0..1023
                const int row = rem >> 2, ch = rem & 3;
                int q = q0 + row;
                int sz = (q < TDIM) ? 16 : 0;
                if (q >= TDIM) q = 0;
                const __half* src = Qh + (size_t)q * CDIM + k0 + ch * 8;
                CP16Z(stb + 10240 + row * 80 + ch * 16, src, sz);
            }
        }
    };

    load_stage(0, sb);
    CP_COMMIT();
    load_stage(1, sb + QKSTAGE);
    CP_COMMIT();

#pragma unroll 1
    for (int s = 0; s < 32; s++) {
        if (s < 31) { CP_WAIT1(); } else { CP_WAIT0(); }
        __syncthreads();
        if (s + 2 < 32) {
            load_stage(s + 2, sb + ((s + 2) % 3) * QKSTAGE);
            CP_COMMIT();
        }
        const char* st = smem + (s % 3) * QKSTAGE;
        const char* Ah = st;
        const char* Al = st + 5120;
        const char* Bh = st + 10240;

#pragma unroll
        for (int kk = 0; kk < 32; kk += 16) {
            uint32_t ah[2][4], al[2][4];
#pragma unroll
            for (int i = 0; i < 2; i++) {
                const int b0 = (wm * 32 + i * 16 + g) * 80 + kk * 2 + t4 * 4;
                ah[i][0] = *(const uint32_t*)(Ah + b0);
                ah[i][1] = *(const uint32_t*)(Ah + b0 + 640);
                ah[i][2] = *(const uint32_t*)(Ah + b0 + 16);
                ah[i][3] = *(const uint32_t*)(Ah + b0 + 656);
                al[i][0] = *(const uint32_t*)(Al + b0);
                al[i][1] = *(const uint32_t*)(Al + b0 + 640);
                al[i][2] = *(const uint32_t*)(Al + b0 + 16);
                al[i][3] = *(const uint32_t*)(Al + b0 + 656);
            }
#pragma unroll
            for (int jj = 0; jj < 2; jj++) {
                uint32_t bh[4][2];
#pragma unroll
                for (int j = 0; j < 4; j++) {
                    const int bb = (wn * 64 + jj * 32 + j * 8 + g) * 80 + kk * 2 + t4 * 4;
                    bh[j][0] = *(const uint32_t*)(Bh + bb);
                    bh[j][1] = *(const uint32_t*)(Bh + bb + 16);
                }
#pragma unroll
                for (int i = 0; i < 2; i++)
#pragma unroll
                    for (int j = 0; j < 4; j++) {
                        float* c = acc[i][jj * 4 + j];
                        mma_f16(c, ah[i], bh[j]);
                        mma_f16(c, al[i], bh[j]);
                    }
            }
        }
    }

    // epilogue: decay + mask, split hi/lo fp16, store P
    const float lg = log2f(GAMMA);
    __half* Phb = g_Ph + ((size_t)h * NTIL + tile) * TT * KQ;
    __half* Plb = g_Pl + ((size_t)h * NTIL + tile) * TT * KQ;
#pragma unroll
    for (int i = 0; i < 2; i++) {
#pragma unroll
        for (int rr = 0; rr < 2; rr++) {
            const int tl = wm * 32 + i * 16 + g + rr * 8;
            const int t  = t0 + tl;
#pragma unroll
            for (int j = 0; j < 8; j++) {
                const int ql = qc * 256 + wn * 64 + j * 8 + 2 * t4;
                const int q  = t0 + ql;
                float v0 = acc[i][j][2 * rr];
                float v1 = acc[i][j][2 * rr + 1];
                int wd0 = q - t, wd1 = wd0 + 1;
                v0 = (wd0 >= 0 && wd0 < WIN && q < TDIM)
                     ? v0 * exp2f((float)wd0 * lg) : 0.f;
                v1 = (wd1 >= 0 && wd1 < WIN && (q + 1) < TDIM)
                     ? v1 * exp2f((float)wd1 * lg) : 0.f;
                uint32_t lo, hi = pack_h2_split(v0, v1, lo);
                size_t idx = ((size_t)tl * KQ + ql) >> 1;
                ((uint32_t*)Phb)[idx] = hi;
                ((uint32_t*)Plb)[idx] = lo;
            }
        }
    }
}

// ---------------------------------------------------------------------------
// av_mma: out[t][c] = sum_{h,q} P * V.  A = P hi/lo, B = V_T hi.
// M=64(t) N=256(c) K=4096. stage: Ah@0(5120) Al@5120 Bv@10240(20480)
// ---------------------------------------------------------------------------
#define AVSTAGE 30720
#define SMEM_AV (3 * AVSTAGE)

__global__ __launch_bounds__(256, 1) void av_mma(float* __restrict__ out)
{
    extern __shared__ char smem[];
    const uint32_t sb = smem_u32(smem);
    const int tid = threadIdx.x;
    const int wid = tid >> 5;
    const int lane = tid & 31;
    const int wm = wid & 1, wn = wid >> 1;
    const int g = lane >> 2, t4 = lane & 3;

    const int cc   = blockIdx.x;      // 0..3
    const int tile = blockIdx.y;
    const int t0   = tile * TT;
    const int c0   = cc * 256;

    float acc[2][8][4];
#pragma unroll
    for (int i = 0; i < 2; i++)
#pragma unroll
        for (int j = 0; j < 8; j++)
#pragma unroll
            for (int q = 0; q < 4; q++) acc[i][j][q] = 0.f;

    auto load_stage = [&](int s, uint32_t stb) {
        const int kk0 = s * 32;
        const int h   = kk0 >> 9;
        const int ql  = kk0 & 511;
#pragma unroll
        for (int i = 0; i < 6; i++) {
            const int c = tid + i * 256;
            if (c < 512) {
                const int mat = c >> 8, rem = c & 255;
                const int row = rem >> 2, ch = rem & 3;
                const __half* src = (mat ? g_Pl : g_Ph)
                    + ((size_t)h * NTIL + tile) * TT * KQ
                    + (size_t)row * KQ + ql + ch * 8;
                CP16(stb + mat * 5120 + row * 80 + ch * 16, src);
            } else {
                const int rem = c - 512;                 // 0..1023
                const int row = rem >> 2, ch = rem & 3;  // row 0..255 (c-dim)
                int tg = t0 + ql + ch * 8;
                int sz = (tg < TDIM) ? 16 : 0;
                if (tg >= TDIM) tg = 0;
                const __half* src = g_Vth
                    + ((size_t)h * CDIM + c0 + row) * TDIM + tg;
                CP16Z(stb + 10240 + row * 80 + ch * 16, src, sz);
            }
        }
    };

    load_stage(0, sb);
    CP_COMMIT();
    load_stage(1, sb + AVSTAGE);
    CP_COMMIT();

#pragma unroll 1
    for (int s = 0; s < 128; s++) {
        if (s < 127) { CP_WAIT1(); } else { CP_WAIT0(); }
        __syncthreads();
        if (s + 2 < 128) {
            load_stage(s + 2, sb + ((s + 2) % 3) * AVSTAGE);
            CP_COMMIT();
        }
        const char* st = smem + (s % 3) * AVSTAGE;
        const char* Ah = st;
        const char* Al = st + 5120;
        const char* Bh = st + 10240;

#pragma unroll
        for (int kk = 0; kk < 32; kk += 16) {
            uint32_t ah[2][4], al[2][4];
#pragma unroll
            for (int i = 0; i < 2; i++) {
                const int b0 = (wm * 32 + i * 16 + g) * 80 + kk * 2 + t4 * 4;
                ah[i][0] = *(const uint32_t*)(Ah + b0);
                ah[i][1] = *(const uint32_t*)(Ah + b0 + 640);
                ah[i][2] = *(const uint32_t*)(Ah + b0 + 16);
                ah[i][3] = *(const uint32_t*)(Ah + b0 + 656);
                al[i][0] = *(const uint32_t*)(Al + b0);
                al[i][1] = *(const uint32_t*)(Al + b0 + 640);
                al[i][2] = *(const uint32_t*)(Al + b0 + 16);
                al[i][3] = *(const uint32_t*)(Al + b0 + 656);
            }
#pragma unroll
            for (int jj = 0; jj < 2; jj++) {
                uint32_t bh[4][2];
#pragma unroll
                for (int j = 0; j < 4; j++) {
                    const int bb = (wn * 64 + jj * 32 + j * 8 + g) * 80 + kk * 2 + t4 * 4;
                    bh[j][0] = *(const uint32_t*)(Bh + bb);
                    bh[j][1] = *(const uint32_t*)(Bh + bb + 16);
                }
#pragma unroll
                for (int i = 0; i < 2; i++)
#pragma unroll
                    for (int j = 0; j < 4; j++) {
                        float* c = acc[i][jj * 4 + j];
                        mma_f16(c, ah[i], bh[j]);
                        mma_f16(c, al[i], bh[j]);
                    }
            }
        }
    }

    // epilogue: fp32 out
#pragma unroll
    for (int i = 0; i < 2; i++) {
#pragma unroll
        for (int rr = 0; rr < 2; rr++) {
            const int t = t0 + wm * 32 + i * 16 + g + rr * 8;
#pragma unroll
            for (int j = 0; j < 8; j++) {
                const int c = c0 + wn * 64 + j * 8 + 2 * t4;
                *(float2*)(out + (size_t)t * CDIM + c) =
                    make_float2(acc[i][j][2 * rr], acc[i][j][2 * rr + 1]);
            }
        }
    }
}

// ---------------------------------------------------------------------------
// GroupNorm in place on out
// ---------------------------------------------------------------------------
__global__ __launch_bounds__(256) void gn_kernel(
    float* __restrict__ out,
    const float* __restrict__ wgt,
    const float* __restrict__ bias)
{
    const int t = blockIdx.x;
    const int tid = threadIdx.x;

    float4 v = *(float4*)(out + (size_t)t * CDIM + tid * 4);
    float s  = v.x + v.y + v.z + v.w;
    float sq = v.x * v.x + v.y * v.y + v.z * v.z + v.w * v.w;

#pragma unroll
    for (int off = 8; off > 0; off >>= 1) {
        s  += __shfl_down_sync(0xffffffffu, s,  off, 16);
        sq += __shfl_down_sync(0xffffffffu, sq, off, 16);
    }
    s  = __shfl_sync(0xffffffffu, s,  0, 16);
    sq = __shfl_sync(0xffffffffu, sq, 0, 16);

    float mean = s * (1.f / 64.f);
    float var  = sq * (1.f / 64.f) - mean * mean;
    float rs   = rsqrtf(var + 1e-5f);

    float4 w4 = *(const float4*)(wgt + tid * 4);
    float4 b4 = *(const float4*)(bias + tid * 4);
    v.x = (v.x - mean) * rs * w4.x + b4.x;
    v.y = (v.y - mean) * rs * w4.y + b4.y;
    v.z = (v.z - mean) * rs * w4.z + b4.z;
    v.w = (v.w - mean) * rs * w4.w + b4.w;
    *(float4*)(out + (size_t)t * CDIM + tid * 4) = v;
}

// ---------------------------------------------------------------------------
extern "C" void kernel_launch(void* const* d_in, const int* in_sizes, int n_in,
                              void* d_out, int out_size)
{
    const float* X  = (const float*)d_in[0];
    const float* Wq = (const float*)d_in[1];
    const float* Wk = (const float*)d_in[2];
    const float* Wv = (const float*)d_in[3];
    const float* gw = (const float*)d_in[4];
    const float* gb = (const float*)d_in[5];
    float* out = (float*)d_out;

    prep_x<<<(TDIM * CDIM / 4) / 256, 256>>>(X);
    prep_w<<<dim3(NW / 32, CDIM / 32, 3), dim3(32, 8)>>>(Wq, Wk, Wv);

    cudaFuncSetAttribute(proj_mma, cudaFuncAttributeMaxDynamicSharedMemorySize,
                         SMEM_PROJ);
    proj_mma<<<dim3(16, 32, 3), 256, SMEM_PROJ>>>();

    transpose_v<<<dim3(CDIM / 32, TDIM / 32, HN), dim3(32, 8)>>>();

    cudaFuncSetAttribute(qk_mma, cudaFuncAttributeMaxDynamicSharedMemorySize,
                         SMEM_QK);
    qk_mma<<<dim3(2, NTIL, HN), 256, SMEM_QK>>>();

    cudaFuncSetAttribute(av_mma, cudaFuncAttributeMaxDynamicSharedMemorySize,
                         SMEM_AV);
    av_mma<<<dim3(4, NTIL), 256, SMEM_AV>>>(out);

    gn_kernel<<<TDIM, 256>>>(out, gw, gb);
}

// round 8
// speedup vs baseline: 2.7422x; 1.2007x over previous
#include <cuda_runtime.h>
#include <cuda_fp16.h>
#include <math.h>
#include <stdint.h>

#define TDIM 2048
#define CDIM 1024
#define HN   8
#define NW   8192
#define WIN  448
#define KQ   512
#define TT   64
#define NTIL 32
#define GAMMA 0.96875f

// fp16 operands.  K and P are split hi/lo (exact A-sides); X, W, Q, V single.
__device__ __half g_Xh[(size_t)TDIM * CDIM];
__device__ __half g_Wth[(size_t)3 * NW * CDIM];            // [z][n][k] single
__device__ __half g_Qh[(size_t)HN * TDIM * CDIM];          // single (B of qk)
__device__ __half g_Kh[(size_t)HN * TDIM * CDIM];          // split (A of qk)
__device__ __half g_Kl[(size_t)HN * TDIM * CDIM];
__device__ __half g_Vh[(size_t)HN * TDIM * CDIM];          // [h][t][c] single
__device__ __half g_Vth[(size_t)HN * CDIM * TDIM];         // [h][c][t] single
__device__ __half g_Ph[(size_t)HN * NTIL * TT * KQ];       // split (A of av)
__device__ __half g_Pl[(size_t)HN * NTIL * TT * KQ];

// ---------------------------------------------------------------------------
#define CP16(dst, src) \
    asm volatile("cp.async.cg.shared.global [%0], [%1], 16;" :: "r"(dst), "l"(src))
#define CP16Z(dst, src, sz) \
    asm volatile("cp.async.cg.shared.global [%0], [%1], 16, %2;" :: "r"(dst), "l"(src), "r"(sz))
#define CP_COMMIT() asm volatile("cp.async.commit_group;" ::: "memory")
#define CP_WAIT1()  asm volatile("cp.async.wait_group 1;" ::: "memory")
#define CP_WAIT0()  asm volatile("cp.async.wait_group 0;" ::: "memory")

__device__ __forceinline__ uint32_t smem_u32(const void* p) {
    uint32_t a;
    asm("{ .reg .u64 t; cvta.to.shared.u64 t, %1; cvt.u32.u64 %0, t; }"
        : "=r"(a) : "l"(p));
    return a;
}

__device__ __forceinline__ void mma_f16(float c[4], const uint32_t a[4],
                                        const uint32_t b[2]) {
    asm volatile(
        "mma.sync.aligned.m16n8k16.row.col.f32.f16.f16.f32 "
        "{%0,%1,%2,%3}, {%4,%5,%6,%7}, {%8,%9}, {%0,%1,%2,%3};"
        : "+f"(c[0]), "+f"(c[1]), "+f"(c[2]), "+f"(c[3])
        : "r"(a[0]), "r"(a[1]), "r"(a[2]), "r"(a[3]), "r"(b[0]), "r"(b[1]));
}

__device__ __forceinline__ uint32_t pack_h2(float v0, float v1) {
    __half2 h = __floats2half2_rn(v0, v1);
    return *(uint32_t*)&h;
}
__device__ __forceinline__ uint32_t pack_h2_split(float v0, float v1, uint32_t& lo) {
    __half h0 = __float2half_rn(v0), h1 = __float2half_rn(v1);
    __half l0 = __float2half_rn(v0 - __half2float(h0));
    __half l1 = __float2half_rn(v1 - __half2float(h1));
    lo = (uint32_t)*(unsigned short*)&l0 | ((uint32_t)*(unsigned short*)&l1 << 16);
    return (uint32_t)*(unsigned short*)&h0 | ((uint32_t)*(unsigned short*)&h1 << 16);
}

// ---------------------------------------------------------------------------
// Prep: X -> fp16 (single)
// ---------------------------------------------------------------------------
__global__ __launch_bounds__(256) void prep_x(const float* __restrict__ X)
{
    int i = blockIdx.x * 256 + threadIdx.x;
    float4 v = ((const float4*)X)[i];
    ((uint2*)g_Xh)[i] = make_uint2(pack_h2(v.x, v.y), pack_h2(v.z, v.w));
}

// ---------------------------------------------------------------------------
// Prep: transpose W [K,N] -> Wt [N,K], single fp16
// ---------------------------------------------------------------------------
__global__ __launch_bounds__(256) void prep_w(
    const float* __restrict__ Wq, const float* __restrict__ Wk,
    const float* __restrict__ Wv)
{
    const int z = blockIdx.z;
    const float* W = (z == 0) ? Wq : ((z == 1) ? Wk : Wv);
    const int n0 = blockIdx.x * 32;
    const int k0 = blockIdx.y * 32;

    __shared__ float t[32][33];
    const int tx = threadIdx.x, ty = threadIdx.y;
#pragma unroll
    for (int j = 0; j < 4; j++)
        t[ty + 8 * j][tx] = W[(size_t)(k0 + ty + 8 * j) * NW + n0 + tx];
    __syncthreads();
#pragma unroll
    for (int j = 0; j < 4; j++) {
        float v = t[tx][ty + 8 * j];
        size_t o = ((size_t)z * NW + n0 + ty + 8 * j) * CDIM + k0 + tx;
        g_Wth[o] = __float2half_rn(v);
    }
}

// ---------------------------------------------------------------------------
// Projection: single-term fp16 (X single x W single), fused RoPE+SiLU,
// outputs: Q hi, K hi+lo, V hi.  CTA tile M=128 N=256 Kstage=32, 3-stage.
// stage: Ah[128][80B]@0 (10240) | Bh[256][80B]@10240 (20480); stage 30720.
// ---------------------------------------------------------------------------
#define PSTAGE 30720
#define SMEM_PROJ (3 * PSTAGE)

__device__ __forceinline__ void proj_load_stage(
    uint32_t stb, int tid, int m0, int zn0, int k0)
{
#pragma unroll
    for (int i = 0; i < 6; i++) {
        const int c = tid + i * 256;
        if (c < 512) {
            const int row = c >> 2;
            const int ch  = c & 3;
            const __half* src = g_Xh + (size_t)(m0 + row) * CDIM + k0 + ch * 8;
            CP16(stb + row * 80 + ch * 16, src);
        } else {
            const int rem = c - 512;
            const int row = rem >> 2;
            const int ch  = rem & 3;
            const __half* src = g_Wth + (size_t)(zn0 + row) * CDIM + k0 + ch * 8;
            CP16(stb + 10240 + row * 80 + ch * 16, src);
        }
    }
}

__global__ __launch_bounds__(256, 1) void proj_mma()
{
    extern __shared__ char smem[];
    const uint32_t sb = smem_u32(smem);
    const int tid = threadIdx.x;
    const int wid = tid >> 5;
    const int lane = tid & 31;
    const int wm = wid & 1, wn = wid >> 1;
    const int g = lane >> 2, t4 = lane & 3;

    const int m0 = blockIdx.x * 128;
    const int n0 = blockIdx.y * 256;
    const int z  = blockIdx.z;
    const int zn0 = z * NW + n0;

    float acc[4][8][4];
#pragma unroll
    for (int i = 0; i < 4; i++)
#pragma unroll
        for (int j = 0; j < 8; j++)
#pragma unroll
            for (int q = 0; q < 4; q++) acc[i][j][q] = 0.f;

    proj_load_stage(sb, tid, m0, zn0, 0);
    CP_COMMIT();
    proj_load_stage(sb + PSTAGE, tid, m0, zn0, 32);
    CP_COMMIT();

#pragma unroll 1
    for (int s = 0; s < 32; s++) {
        if (s < 31) { CP_WAIT1(); } else { CP_WAIT0(); }
        __syncthreads();
        if (s + 2 < 32) {
            proj_load_stage(sb + ((s + 2) % 3) * PSTAGE, tid, m0, zn0, (s + 2) * 32);
            CP_COMMIT();
        }
        const char* st = smem + (s % 3) * PSTAGE;
        const char* Ah = st;
        const char* Bh = st + 10240;

#pragma unroll
        for (int kk = 0; kk < 32; kk += 16) {
            uint32_t ah[4][4];
#pragma unroll
            for (int i = 0; i < 4; i++) {
                const int b0 = (wm * 64 + i * 16 + g) * 80 + kk * 2 + t4 * 4;
                ah[i][0] = *(const uint32_t*)(Ah + b0);
                ah[i][1] = *(const uint32_t*)(Ah + b0 + 640);
                ah[i][2] = *(const uint32_t*)(Ah + b0 + 16);
                ah[i][3] = *(const uint32_t*)(Ah + b0 + 656);
            }
#pragma unroll
            for (int jj = 0; jj < 2; jj++) {
                uint32_t bh[4][2];
#pragma unroll
                for (int j = 0; j < 4; j++) {
                    const int bb = (wn * 64 + jj * 32 + j * 8 + g) * 80 + kk * 2 + t4 * 4;
                    bh[j][0] = *(const uint32_t*)(Bh + bb);
                    bh[j][1] = *(const uint32_t*)(Bh + bb + 16);
                }
#pragma unroll
                for (int i = 0; i < 4; i++)
#pragma unroll
                    for (int j = 0; j < 4; j++)
                        mma_f16(acc[i][jj * 4 + j], ah[i], bh[j]);
            }
        }
    }

    // epilogue: RoPE (Q,K cols<64) + SiLU, fp16 store (lo only for K)
    const int h  = n0 >> 10;
    const int cbase = (n0 & 1023) + wn * 64 + 2 * t4;
    const bool rope_blk = (z < 2) && ((n0 & 1023) == 0) && (wn == 0);

    __half* Hi = (z == 0) ? g_Qh : ((z == 1) ? g_Kh : g_Vh);
    Hi += (size_t)h * TDIM * CDIM;
    __half* Lo = g_Kl + (size_t)h * TDIM * CDIM;

#pragma unroll
    for (int i = 0; i < 4; i++) {
#pragma unroll
        for (int rr = 0; rr < 2; rr++) {
            const int r = m0 + wm * 64 + i * 16 + g + rr * 8;
#pragma unroll
            for (int j = 0; j < 8; j++) {
                const int col = cbase + j * 8;
                float v0 = acc[i][j][2 * rr];
                float v1 = acc[i][j][2 * rr + 1];
                if (rope_blk) {
                    int c2 = col >> 1;
                    float invf = (float)exp(-((double)(2 * c2) / 64.0) * log(10000.0));
                    float ang = (float)r * invf;
                    float sn, cs;
                    sincosf(ang, &sn, &cs);
                    float y0 = v0 * cs - v1 * sn;
                    float y1 = v1 * cs + v0 * sn;
                    v0 = y0; v1 = y1;
                }
                v0 = v0 / (1.f + expf(-v0));
                v1 = v1 / (1.f + expf(-v1));
                size_t idx = ((size_t)r * CDIM + col) >> 1;
                if (z == 1) {
                    uint32_t lo, hi = pack_h2_split(v0, v1, lo);
                    ((uint32_t*)Hi)[idx] = hi;
                    ((uint32_t*)Lo)[idx] = lo;
                } else {
                    ((uint32_t*)Hi)[idx] = pack_h2(v0, v1);
                }
            }
        }
    }
}

// ---------------------------------------------------------------------------
// V transpose: [h][t][c] -> [h][c][t]
// ---------------------------------------------------------------------------
__global__ void transpose_v()
{
    __shared__ unsigned short sh[32][33];
    const int c0 = blockIdx.x * 32;
    const int t0 = blockIdx.y * 32;
    const int h  = blockIdx.z;
    const int tx = threadIdx.x, ty = threadIdx.y;

    const unsigned short* Vh = (const unsigned short*)g_Vh + (size_t)h * TDIM * CDIM;
#pragma unroll
    for (int k = 0; k < 4; k++) {
        int r = ty + 8 * k;
        sh[r][tx] = Vh[(size_t)(t0 + r) * CDIM + c0 + tx];
    }
    __syncthreads();
    unsigned short* Th = (unsigned short*)g_Vth + (size_t)h * CDIM * TDIM;
#pragma unroll
    for (int k = 0; k < 4; k++) {
        int r = ty + 8 * k;
        Th[(size_t)(c0 + r) * TDIM + t0 + tx] = sh[tx][r];
    }
}

// ---------------------------------------------------------------------------
// qk_mma: P = decay * (K Q^T).  A = K hi/lo (split), B = Q (single).
// M=64(t) N=256(q) K=1024. stage: Ah@0(5120) Al@5120 Bq@10240(20480)
// ---------------------------------------------------------------------------
#define QKSTAGE 30720
#define SMEM_QK (3 * QKSTAGE)

__global__ __launch_bounds__(256, 1) void qk_mma()
{
    extern __shared__ char smem[];
    const uint32_t sb = smem_u32(smem);
    const int tid = threadIdx.x;
    const int wid = tid >> 5;
    const int lane = tid & 31;
    const int wm = wid & 1, wn = wid >> 1;
    const int g = lane >> 2, t4 = lane & 3;

    const int qc   = blockIdx.x;          // 0..1
    const int tile = blockIdx.y;
    const int h    = blockIdx.z;
    const int t0   = tile * TT;
    const int q0   = t0 + qc * 256;

    const __half* Kh = g_Kh + (size_t)h * TDIM * CDIM;
    const __half* Kl = g_Kl + (size_t)h * TDIM * CDIM;
    const __half* Qh = g_Qh + (size_t)h * TDIM * CDIM;

    float acc[2][8][4];
#pragma unroll
    for (int i = 0; i < 2; i++)
#pragma unroll
        for (int j = 0; j < 8; j++)
#pragma unroll
            for (int q = 0; q < 4; q++) acc[i][j][q] = 0.f;

    auto load_stage = [&](int s, uint32_t stb) {
        const int k0 = s * 32;
#pragma unroll
        for (int i = 0; i < 6; i++) {
            const int c = tid + i * 256;
            if (c < 512) {
                const int mat = c >> 8, rem = c & 255;
                const int row = rem >> 2, ch = rem & 3;
                const __half* src = (mat ? Kl : Kh)
                    + (size_t)(t0 + row) * CDIM + k0 + ch * 8;
                CP16(stb + mat * 5120 + row * 80 + ch * 16, src);
            } else {
                const int rem = c - 512;                 // 0..1023
                const int row = rem >> 2, ch = rem & 3;
                int q = q0 + row;
                int sz = (q < TDIM) ? 16 : 0;
                if (q >= TDIM) q = 0;
                const __half* src = Qh + (size_t)q * CDIM + k0 + ch * 8;
                CP16Z(stb + 10240 + row * 80 + ch * 16, src, sz);
            }
        }
    };

    load_stage(0, sb);
    CP_COMMIT();
    load_stage(1, sb + QKSTAGE);
    CP_COMMIT();

#pragma unroll 1
    for (int s = 0; s < 32; s++) {
        if (s < 31) { CP_WAIT1(); } else { CP_WAIT0(); }
        __syncthreads();
        if (s + 2 < 32) {
            load_stage(s + 2, sb + ((s + 2) % 3) * QKSTAGE);
            CP_COMMIT();
        }
        const char* st = smem + (s % 3) * QKSTAGE;
        const char* Ah = st;
        const char* Al = st + 5120;
        const char* Bh = st + 10240;

#pragma unroll
        for (int kk = 0; kk < 32; kk += 16) {
            uint32_t ah[2][4], al[2][4];
#pragma unroll
            for (int i = 0; i < 2; i++) {
                const int b0 = (wm * 32 + i * 16 + g) * 80 + kk * 2 + t4 * 4;
                ah[i][0] = *(const uint32_t*)(Ah + b0);
                ah[i][1] = *(const uint32_t*)(Ah + b0 + 640);
                ah[i][2] = *(const uint32_t*)(Ah + b0 + 16);
                ah[i][3] = *(const uint32_t*)(Ah + b0 + 656);
                al[i][0] = *(const uint32_t*)(Al + b0);
                al[i][1] = *(const uint32_t*)(Al + b0 + 640);
                al[i][2] = *(const uint32_t*)(Al + b0 + 16);
                al[i][3] = *(const uint32_t*)(Al + b0 + 656);
            }
#pragma unroll
            for (int jj = 0; jj < 2; jj++) {
                uint32_t bh[4][2];
#pragma unroll
                for (int j = 0; j < 4; j++) {
                    const int bb = (wn * 64 + jj * 32 + j * 8 + g) * 80 + kk * 2 + t4 * 4;
                    bh[j][0] = *(const uint32_t*)(Bh + bb);
                    bh[j][1] = *(const uint32_t*)(Bh + bb + 16);
                }
#pragma unroll
                for (int i = 0; i < 2; i++)
#pragma unroll
                    for (int j = 0; j < 4; j++) {
                        float* c = acc[i][jj * 4 + j];
                        mma_f16(c, ah[i], bh[j]);
                        mma_f16(c, al[i], bh[j]);
                    }
            }
        }
    }

    // epilogue: decay + mask, split hi/lo fp16, store P
    const float lg = log2f(GAMMA);
    __half* Phb = g_Ph + ((size_t)h * NTIL + tile) * TT * KQ;
    __half* Plb = g_Pl + ((size_t)h * NTIL + tile) * TT * KQ;
#pragma unroll
    for (int i = 0; i < 2; i++) {
#pragma unroll
        for (int rr = 0; rr < 2; rr++) {
            const int tl = wm * 32 + i * 16 + g + rr * 8;
            const int t  = t0 + tl;
#pragma unroll
            for (int j = 0; j < 8; j++) {
                const int ql = qc * 256 + wn * 64 + j * 8 + 2 * t4;
                const int q  = t0 + ql;
                float v0 = acc[i][j][2 * rr];
                float v1 = acc[i][j][2 * rr + 1];
                int wd0 = q - t, wd1 = wd0 + 1;
                v0 = (wd0 >= 0 && wd0 < WIN && q < TDIM)
                     ? v0 * exp2f((float)wd0 * lg) : 0.f;
                v1 = (wd1 >= 0 && wd1 < WIN && (q + 1) < TDIM)
                     ? v1 * exp2f((float)wd1 * lg) : 0.f;
                uint32_t lo, hi = pack_h2_split(v0, v1, lo);
                size_t idx = ((size_t)tl * KQ + ql) >> 1;
                ((uint32_t*)Phb)[idx] = hi;
                ((uint32_t*)Plb)[idx] = lo;
            }
        }
    }
}

// ---------------------------------------------------------------------------
// av_mma: out[t][c] = sum_{h,q} P * V.  A = P hi/lo, B = V_T.
// M=64(t) N=256(c) K=4096. stage: Ah@0(5120) Al@5120 Bv@10240(20480)
// ---------------------------------------------------------------------------
#define AVSTAGE 30720
#define SMEM_AV (3 * AVSTAGE)

__global__ __launch_bounds__(256, 1) void av_mma(float* __restrict__ out)
{
    extern __shared__ char smem[];
    const uint32_t sb = smem_u32(smem);
    const int tid = threadIdx.x;
    const int wid = tid >> 5;
    const int lane = tid & 31;
    const int wm = wid & 1, wn = wid >> 1;
    const int g = lane >> 2, t4 = lane & 3;

    const int cc   = blockIdx.x;      // 0..3
    const int tile = blockIdx.y;
    const int t0   = tile * TT;
    const int c0   = cc * 256;

    float acc[2][8][4];
#pragma unroll
    for (int i = 0; i < 2; i++)
#pragma unroll
        for (int j = 0; j < 8; j++)
#pragma unroll
            for (int q = 0; q < 4; q++) acc[i][j][q] = 0.f;

    auto load_stage = [&](int s, uint32_t stb) {
        const int kk0 = s * 32;
        const int h   = kk0 >> 9;
        const int ql  = kk0 & 511;
#pragma unroll
        for (int i = 0; i < 6; i++) {
            const int c = tid + i * 256;
            if (c < 512) {
                const int mat = c >> 8, rem = c & 255;
                const int row = rem >> 2, ch = rem & 3;
                const __half* src = (mat ? g_Pl : g_Ph)
                    + ((size_t)h * NTIL + tile) * TT * KQ
                    + (size_t)row * KQ + ql + ch * 8;
                CP16(stb + mat * 5120 + row * 80 + ch * 16, src);
            } else {
                const int rem = c - 512;                 // 0..1023
                const int row = rem >> 2, ch = rem & 3;  // row 0..255 (c-dim)
                int tg = t0 + ql + ch * 8;
                int sz = (tg < TDIM) ? 16 : 0;
                if (tg >= TDIM) tg = 0;
                const __half* src = g_Vth
                    + ((size_t)h * CDIM + c0 + row) * TDIM + tg;
                CP16Z(stb + 10240 + row * 80 + ch * 16, src, sz);
            }
        }
    };

    load_stage(0, sb);
    CP_COMMIT();
    load_stage(1, sb + AVSTAGE);
    CP_COMMIT();

#pragma unroll 1
    for (int s = 0; s < 128; s++) {
        if (s < 127) { CP_WAIT1(); } else { CP_WAIT0(); }
        __syncthreads();
        if (s + 2 < 128) {
            load_stage(s + 2, sb + ((s + 2) % 3) * AVSTAGE);
            CP_COMMIT();
        }
        const char* st = smem + (s % 3) * AVSTAGE;
        const char* Ah = st;
        const char* Al = st + 5120;
        const char* Bh = st + 10240;

#pragma unroll
        for (int kk = 0; kk < 32; kk += 16) {
            uint32_t ah[2][4], al[2][4];
#pragma unroll
            for (int i = 0; i < 2; i++) {
                const int b0 = (wm * 32 + i * 16 + g) * 80 + kk * 2 + t4 * 4;
                ah[i][0] = *(const uint32_t*)(Ah + b0);
                ah[i][1] = *(const uint32_t*)(Ah + b0 + 640);
                ah[i][2] = *(const uint32_t*)(Ah + b0 + 16);
                ah[i][3] = *(const uint32_t*)(Ah + b0 + 656);
                al[i][0] = *(const uint32_t*)(Al + b0);
                al[i][1] = *(const uint32_t*)(Al + b0 + 640);
                al[i][2] = *(const uint32_t*)(Al + b0 + 16);
                al[i][3] = *(const uint32_t*)(Al + b0 + 656);
            }
#pragma unroll
            for (int jj = 0; jj < 2; jj++) {
                uint32_t bh[4][2];
#pragma unroll
                for (int j = 0; j < 4; j++) {
                    const int bb = (wn * 64 + jj * 32 + j * 8 + g) * 80 + kk * 2 + t4 * 4;
                    bh[j][0] = *(const uint32_t*)(Bh + bb);
                    bh[j][1] = *(const uint32_t*)(Bh + bb + 16);
                }
#pragma unroll
                for (int i = 0; i < 2; i++)
#pragma unroll
                    for (int j = 0; j < 4; j++) {
                        float* c = acc[i][jj * 4 + j];
                        mma_f16(c, ah[i], bh[j]);
                        mma_f16(c, al[i], bh[j]);
                    }
            }
        }
    }

    // epilogue: fp32 out
#pragma unroll
    for (int i = 0; i < 2; i++) {
#pragma unroll
        for (int rr = 0; rr < 2; rr++) {
            const int t = t0 + wm * 32 + i * 16 + g + rr * 8;
#pragma unroll
            for (int j = 0; j < 8; j++) {
                const int c = c0 + wn * 64 + j * 8 + 2 * t4;
                *(float2*)(out + (size_t)t * CDIM + c) =
                    make_float2(acc[i][j][2 * rr], acc[i][j][2 * rr + 1]);
            }
        }
    }
}

// ---------------------------------------------------------------------------
// GroupNorm in place on out
// ---------------------------------------------------------------------------
__global__ __launch_bounds__(256) void gn_kernel(
    float* __restrict__ out,
    const float* __restrict__ wgt,
    const float* __restrict__ bias)
{
    const int t = blockIdx.x;
    const int tid = threadIdx.x;

    float4 v = *(float4*)(out + (size_t)t * CDIM + tid * 4);
    float s  = v.x + v.y + v.z + v.w;
    float sq = v.x * v.x + v.y * v.y + v.z * v.z + v.w * v.w;

#pragma unroll
    for (int off = 8; off > 0; off >>= 1) {
        s  += __shfl_down_sync(0xffffffffu, s,  off, 16);
        sq += __shfl_down_sync(0xffffffffu, sq, off, 16);
    }
    s  = __shfl_sync(0xffffffffu, s,  0, 16);
    sq = __shfl_sync(0xffffffffu, sq, 0, 16);

    float mean = s * (1.f / 64.f);
    float var  = sq * (1.f / 64.f) - mean * mean;
    float rs   = rsqrtf(var + 1e-5f);

    float4 w4 = *(const float4*)(wgt + tid * 4);
    float4 b4 = *(const float4*)(bias + tid * 4);
    v.x = (v.x - mean) * rs * w4.x + b4.x;
    v.y = (v.y - mean) * rs * w4.y + b4.y;
    v.z = (v.z - mean) * rs * w4.z + b4.z;
    v.w = (v.w - mean) * rs * w4.w + b4.w;
    *(float4*)(out + (size_t)t * CDIM + tid * 4) = v;
}

// ---------------------------------------------------------------------------
extern "C" void kernel_launch(void* const* d_in, const int* in_sizes, int n_in,
                              void* d_out, int out_size)
{
    const float* X  = (const float*)d_in[0];
    const float* Wq = (const float*)d_in[1];
    const float* Wk = (const float*)d_in[2];
    const float* Wv = (const float*)d_in[3];
    const float* gw = (const float*)d_in[4];
    const float* gb = (const float*)d_in[5];
    float* out = (float*)d_out;

    prep_x<<<(TDIM * CDIM / 4) / 256, 256>>>(X);
    prep_w<<<dim3(NW / 32, CDIM / 32, 3), dim3(32, 8)>>>(Wq, Wk, Wv);

    cudaFuncSetAttribute(proj_mma, cudaFuncAttributeMaxDynamicSharedMemorySize,
                         SMEM_PROJ);
    proj_mma<<<dim3(16, 32, 3), 256, SMEM_PROJ>>>();

    transpose_v<<<dim3(CDIM / 32, TDIM / 32, HN), dim3(32, 8)>>>();

    cudaFuncSetAttribute(qk_mma, cudaFuncAttributeMaxDynamicSharedMemorySize,
                         SMEM_QK);
    qk_mma<<<dim3(2, NTIL, HN), 256, SMEM_QK>>>();

    cudaFuncSetAttribute(av_mma, cudaFuncAttributeMaxDynamicSharedMemorySize,
                         SMEM_AV);
    av_mma<<<dim3(4, NTIL), 256, SMEM_AV>>>(out);

    gn_kernel<<<TDIM, 256>>>(out, gw, gb);
}

// round 9
// speedup vs baseline: 3.2591x; 1.1885x over previous
#include <cuda_runtime.h>
#include <cuda_fp16.h>
#include <math.h>
#include <stdint.h>

#define TDIM 2048
#define CDIM 1024
#define HN   8
#define NW   8192
#define WIN  320
#define KQ   384
#define TT   64
#define NTIL 32
#define GAMMA 0.96875f

// fp16 operands, all single precision (error budget per quadrature model).
__device__ __half g_Xh[(size_t)TDIM * CDIM];
__device__ __half g_Wth[(size_t)3 * NW * CDIM];            // [z][n][k]
__device__ __half g_Qh[(size_t)HN * TDIM * CDIM];
__device__ __half g_Kh[(size_t)HN * TDIM * CDIM];
__device__ __half g_Vh[(size_t)HN * TDIM * CDIM];          // [h][t][c]
__device__ __half g_Vth[(size_t)HN * CDIM * TDIM];         // [h][c][t]
__device__ __half g_Ph[(size_t)HN * NTIL * TT * KQ];       // [h][tile][t][q]

// ---------------------------------------------------------------------------
#define CP16(dst, src) \
    asm volatile("cp.async.cg.shared.global [%0], [%1], 16;" :: "r"(dst), "l"(src))
#define CP16Z(dst, src, sz) \
    asm volatile("cp.async.cg.shared.global [%0], [%1], 16, %2;" :: "r"(dst), "l"(src), "r"(sz))
#define CP_COMMIT() asm volatile("cp.async.commit_group;" ::: "memory")
#define CP_WAIT1()  asm volatile("cp.async.wait_group 1;" ::: "memory")
#define CP_WAIT0()  asm volatile("cp.async.wait_group 0;" ::: "memory")

__device__ __forceinline__ uint32_t smem_u32(const void* p) {
    uint32_t a;
    asm("{ .reg .u64 t; cvta.to.shared.u64 t, %1; cvt.u32.u64 %0, t; }"
        : "=r"(a) : "l"(p));
    return a;
}

__device__ __forceinline__ void mma_f16(float c[4], const uint32_t a[4],
                                        const uint32_t b[2]) {
    asm volatile(
        "mma.sync.aligned.m16n8k16.row.col.f32.f16.f16.f32 "
        "{%0,%1,%2,%3}, {%4,%5,%6,%7}, {%8,%9}, {%0,%1,%2,%3};"
        : "+f"(c[0]), "+f"(c[1]), "+f"(c[2]), "+f"(c[3])
        : "r"(a[0]), "r"(a[1]), "r"(a[2]), "r"(a[3]), "r"(b[0]), "r"(b[1]));
}

__device__ __forceinline__ uint32_t pack_h2(float v0, float v1) {
    __half2 h = __floats2half2_rn(v0, v1);
    return *(uint32_t*)&h;
}

// ---------------------------------------------------------------------------
// Prep: X -> fp16
// ---------------------------------------------------------------------------
__global__ __launch_bounds__(256) void prep_x(const float* __restrict__ X)
{
    int i = blockIdx.x * 256 + threadIdx.x;
    float4 v = ((const float4*)X)[i];
    ((uint2*)g_Xh)[i] = make_uint2(pack_h2(v.x, v.y), pack_h2(v.z, v.w));
}

// ---------------------------------------------------------------------------
// Prep: transpose W [K,N] -> Wt [N,K], fp16
// ---------------------------------------------------------------------------
__global__ __launch_bounds__(256) void prep_w(
    const float* __restrict__ Wq, const float* __restrict__ Wk,
    const float* __restrict__ Wv)
{
    const int z = blockIdx.z;
    const float* W = (z == 0) ? Wq : ((z == 1) ? Wk : Wv);
    const int n0 = blockIdx.x * 32;
    const int k0 = blockIdx.y * 32;

    __shared__ float t[32][33];
    const int tx = threadIdx.x, ty = threadIdx.y;
#pragma unroll
    for (int j = 0; j < 4; j++)
        t[ty + 8 * j][tx] = W[(size_t)(k0 + ty + 8 * j) * NW + n0 + tx];
    __syncthreads();
#pragma unroll
    for (int j = 0; j < 4; j++) {
        float v = t[tx][ty + 8 * j];
        size_t o = ((size_t)z * NW + n0 + ty + 8 * j) * CDIM + k0 + tx;
        g_Wth[o] = __float2half_rn(v);
    }
}

// ---------------------------------------------------------------------------
// Projection: single-term fp16, fused RoPE+SiLU, outputs Q/K/V fp16.
// CTA tile M=128 N=256 Kstage=32, 3-stage pipeline.
// stage: A[128][80B]@0 (10240) | B[256][80B]@10240 (20480); stage 30720.
// ---------------------------------------------------------------------------
#define PSTAGE 30720
#define SMEM_PROJ (3 * PSTAGE)

__device__ __forceinline__ void proj_load_stage(
    uint32_t stb, int tid, int m0, int zn0, int k0)
{
#pragma unroll
    for (int i = 0; i < 6; i++) {
        const int c = tid + i * 256;
        if (c < 512) {
            const int row = c >> 2;
            const int ch  = c & 3;
            const __half* src = g_Xh + (size_t)(m0 + row) * CDIM + k0 + ch * 8;
            CP16(stb + row * 80 + ch * 16, src);
        } else {
            const int rem = c - 512;
            const int row = rem >> 2;
            const int ch  = rem & 3;
            const __half* src = g_Wth + (size_t)(zn0 + row) * CDIM + k0 + ch * 8;
            CP16(stb + 10240 + row * 80 + ch * 16, src);
        }
    }
}

__global__ __launch_bounds__(256, 1) void proj_mma()
{
    extern __shared__ char smem[];
    const uint32_t sb = smem_u32(smem);
    const int tid = threadIdx.x;
    const int wid = tid >> 5;
    const int lane = tid & 31;
    const int wm = wid & 1, wn = wid >> 1;
    const int g = lane >> 2, t4 = lane & 3;

    const int m0 = blockIdx.x * 128;
    const int n0 = blockIdx.y * 256;
    const int z  = blockIdx.z;
    const int zn0 = z * NW + n0;

    float acc[4][8][4];
#pragma unroll
    for (int i = 0; i < 4; i++)
#pragma unroll
        for (int j = 0; j < 8; j++)
#pragma unroll
            for (int q = 0; q < 4; q++) acc[i][j][q] = 0.f;

    proj_load_stage(sb, tid, m0, zn0, 0);
    CP_COMMIT();
    proj_load_stage(sb + PSTAGE, tid, m0, zn0, 32);
    CP_COMMIT();

#pragma unroll 1
    for (int s = 0; s < 32; s++) {
        if (s < 31) { CP_WAIT1(); } else { CP_WAIT0(); }
        __syncthreads();
        if (s + 2 < 32) {
            proj_load_stage(sb + ((s + 2) % 3) * PSTAGE, tid, m0, zn0, (s + 2) * 32);
            CP_COMMIT();
        }
        const char* st = smem + (s % 3) * PSTAGE;
        const char* Ah = st;
        const char* Bh = st + 10240;

#pragma unroll
        for (int kk = 0; kk < 32; kk += 16) {
            uint32_t ah[4][4];
#pragma unroll
            for (int i = 0; i < 4; i++) {
                const int b0 = (wm * 64 + i * 16 + g) * 80 + kk * 2 + t4 * 4;
                ah[i][0] = *(const uint32_t*)(Ah + b0);
                ah[i][1] = *(const uint32_t*)(Ah + b0 + 640);
                ah[i][2] = *(const uint32_t*)(Ah + b0 + 16);
                ah[i][3] = *(const uint32_t*)(Ah + b0 + 656);
            }
#pragma unroll
            for (int jj = 0; jj < 2; jj++) {
                uint32_t bh[4][2];
#pragma unroll
                for (int j = 0; j < 4; j++) {
                    const int bb = (wn * 64 + jj * 32 + j * 8 + g) * 80 + kk * 2 + t4 * 4;
                    bh[j][0] = *(const uint32_t*)(Bh + bb);
                    bh[j][1] = *(const uint32_t*)(Bh + bb + 16);
                }
#pragma unroll
                for (int i = 0; i < 4; i++)
#pragma unroll
                    for (int j = 0; j < 4; j++)
                        mma_f16(acc[i][jj * 4 + j], ah[i], bh[j]);
            }
        }
    }

    // epilogue: RoPE (Q,K cols<64) + SiLU, fp16 store
    const int h  = n0 >> 10;
    const int cbase = (n0 & 1023) + wn * 64 + 2 * t4;
    const bool rope_blk = (z < 2) && ((n0 & 1023) == 0) && (wn == 0);

    __half* Hi = (z == 0) ? g_Qh : ((z == 1) ? g_Kh : g_Vh);
    Hi += (size_t)h * TDIM * CDIM;

#pragma unroll
    for (int i = 0; i < 4; i++) {
#pragma unroll
        for (int rr = 0; rr < 2; rr++) {
            const int r = m0 + wm * 64 + i * 16 + g + rr * 8;
#pragma unroll
            for (int j = 0; j < 8; j++) {
                const int col = cbase + j * 8;
                float v0 = acc[i][j][2 * rr];
                float v1 = acc[i][j][2 * rr + 1];
                if (rope_blk) {
                    int c2 = col >> 1;
                    float invf = (float)exp(-((double)(2 * c2) / 64.0) * log(10000.0));
                    float ang = (float)r * invf;
                    float sn, cs;
                    sincosf(ang, &sn, &cs);
                    float y0 = v0 * cs - v1 * sn;
                    float y1 = v1 * cs + v0 * sn;
                    v0 = y0; v1 = y1;
                }
                v0 = v0 / (1.f + expf(-v0));
                v1 = v1 / (1.f + expf(-v1));
                ((uint32_t*)Hi)[((size_t)r * CDIM + col) >> 1] = pack_h2(v0, v1);
            }
        }
    }
}

// ---------------------------------------------------------------------------
// V transpose: [h][t][c] -> [h][c][t]
// ---------------------------------------------------------------------------
__global__ void transpose_v()
{
    __shared__ unsigned short sh[32][33];
    const int c0 = blockIdx.x * 32;
    const int t0 = blockIdx.y * 32;
    const int h  = blockIdx.z;
    const int tx = threadIdx.x, ty = threadIdx.y;

    const unsigned short* Vh = (const unsigned short*)g_Vh + (size_t)h * TDIM * CDIM;
#pragma unroll
    for (int k = 0; k < 4; k++) {
        int r = ty + 8 * k;
        sh[r][tx] = Vh[(size_t)(t0 + r) * CDIM + c0 + tx];
    }
    __syncthreads();
    unsigned short* Th = (unsigned short*)g_Vth + (size_t)h * CDIM * TDIM;
#pragma unroll
    for (int k = 0; k < 4; k++) {
        int r = ty + 8 * k;
        Th[(size_t)(c0 + r) * TDIM + t0 + tx] = sh[tx][r];
    }
}

// ---------------------------------------------------------------------------
// qk_mma: P = decay * (K Q^T), single-term fp16.
// M=64(t) N=128(q) per block, grid.x=3 covers q in [t0, t0+384), K=1024.
// stage: A[64][80B]@0 (5120) | B[128][80B]@5120 (10240); stage 15360.
// ---------------------------------------------------------------------------
#define QKSTAGE 15360
#define SMEM_QK (3 * QKSTAGE)

__global__ __launch_bounds__(256, 1) void qk_mma()
{
    extern __shared__ char smem[];
    const uint32_t sb = smem_u32(smem);
    const int tid = threadIdx.x;
    const int wid = tid >> 5;
    const int lane = tid & 31;
    const int wm = wid & 1, wn = wid >> 1;
    const int g = lane >> 2, t4 = lane & 3;

    const int qc   = blockIdx.x;          // 0..2
    const int tile = blockIdx.y;
    const int h    = blockIdx.z;
    const int t0   = tile * TT;
    const int q0   = t0 + qc * 128;

    const __half* Kh = g_Kh + (size_t)h * TDIM * CDIM;
    const __half* Qh = g_Qh + (size_t)h * TDIM * CDIM;

    float acc[2][4][4];
#pragma unroll
    for (int i = 0; i < 2; i++)
#pragma unroll
        for (int j = 0; j < 4; j++)
#pragma unroll
            for (int q = 0; q < 4; q++) acc[i][j][q] = 0.f;

    auto load_stage = [&](int s, uint32_t stb) {
        const int k0 = s * 32;
#pragma unroll
        for (int i = 0; i < 3; i++) {
            const int c = tid + i * 256;
            if (c < 256) {
                const int row = c >> 2, ch = c & 3;
                const __half* src = Kh + (size_t)(t0 + row) * CDIM + k0 + ch * 8;
                CP16(stb + row * 80 + ch * 16, src);
            } else {
                const int rem = c - 256;                 // 0..511
                const int row = rem >> 2, ch = rem & 3;
                int q = q0 + row;
                int sz = (q < TDIM) ? 16 : 0;
                if (q >= TDIM) q = 0;
                const __half* src = Qh + (size_t)q * CDIM + k0 + ch * 8;
                CP16Z(stb + 5120 + row * 80 + ch * 16, src, sz);
            }
        }
    };

    load_stage(0, sb);
    CP_COMMIT();
    load_stage(1, sb + QKSTAGE);
    CP_COMMIT();

#pragma unroll 1
    for (int s = 0; s < 32; s++) {
        if (s < 31) { CP_WAIT1(); } else { CP_WAIT0(); }
        __syncthreads();
        if (s + 2 < 32) {
            load_stage(s + 2, sb + ((s + 2) % 3) * QKSTAGE);
            CP_COMMIT();
        }
        const char* st = smem + (s % 3) * QKSTAGE;
        const char* Ah = st;
        const char* Bh = st + 5120;

#pragma unroll
        for (int kk = 0; kk < 32; kk += 16) {
            uint32_t ah[2][4];
#pragma unroll
            for (int i = 0; i < 2; i++) {
                const int b0 = (wm * 32 + i * 16 + g) * 80 + kk * 2 + t4 * 4;
                ah[i][0] = *(const uint32_t*)(Ah + b0);
                ah[i][1] = *(const uint32_t*)(Ah + b0 + 640);
                ah[i][2] = *(const uint32_t*)(Ah + b0 + 16);
                ah[i][3] = *(const uint32_t*)(Ah + b0 + 656);
            }
            uint32_t bh[4][2];
#pragma unroll
            for (int j = 0; j < 4; j++) {
                const int bb = (wn * 32 + j * 8 + g) * 80 + kk * 2 + t4 * 4;
                bh[j][0] = *(const uint32_t*)(Bh + bb);
                bh[j][1] = *(const uint32_t*)(Bh + bb + 16);
            }
#pragma unroll
            for (int i = 0; i < 2; i++)
#pragma unroll
                for (int j = 0; j < 4; j++)
                    mma_f16(acc[i][j], ah[i], bh[j]);
        }
    }

    // epilogue: decay + mask, fp16 store P
    const float lg = log2f(GAMMA);
    __half* Phb = g_Ph + ((size_t)h * NTIL + tile) * TT * KQ;
#pragma unroll
    for (int i = 0; i < 2; i++) {
#pragma unroll
        for (int rr = 0; rr < 2; rr++) {
            const int tl = wm * 32 + i * 16 + g + rr * 8;
            const int t  = t0 + tl;
#pragma unroll
            for (int j = 0; j < 4; j++) {
                const int ql = qc * 128 + wn * 32 + j * 8 + 2 * t4;
                const int q  = t0 + ql;
                float v0 = acc[i][j][2 * rr];
                float v1 = acc[i][j][2 * rr + 1];
                int wd0 = q - t, wd1 = wd0 + 1;
                v0 = (wd0 >= 0 && wd0 < WIN && q < TDIM)
                     ? v0 * exp2f((float)wd0 * lg) : 0.f;
                v1 = (wd1 >= 0 && wd1 < WIN && (q + 1) < TDIM)
                     ? v1 * exp2f((float)wd1 * lg) : 0.f;
                ((uint32_t*)Phb)[((size_t)tl * KQ + ql) >> 1] = pack_h2(v0, v1);
            }
        }
    }
}

// ---------------------------------------------------------------------------
// av_mma: out[t][c] = sum_{h,q} P * V.  Single-term fp16.
// M=64(t) N=256(c) K=8*384=3072. stage: A@0(5120) B@5120(20480); 25600.
// ---------------------------------------------------------------------------
#define AVSTAGE 25600
#define SMEM_AV (3 * AVSTAGE)

__global__ __launch_bounds__(256, 1) void av_mma(float* __restrict__ out)
{
    extern __shared__ char smem[];
    const uint32_t sb = smem_u32(smem);
    const int tid = threadIdx.x;
    const int wid = tid >> 5;
    const int lane = tid & 31;
    const int wm = wid & 1, wn = wid >> 1;
    const int g = lane >> 2, t4 = lane & 3;

    const int cc   = blockIdx.x;      // 0..3
    const int tile = blockIdx.y;
    const int t0   = tile * TT;
    const int c0   = cc * 256;

    float acc[2][8][4];
#pragma unroll
    for (int i = 0; i < 2; i++)
#pragma unroll
        for (int j = 0; j < 8; j++)
#pragma unroll
            for (int q = 0; q < 4; q++) acc[i][j][q] = 0.f;

    auto load_stage = [&](int s, uint32_t stb) {
        const int kk0 = s * 32;
        const int h   = kk0 / KQ;
        const int ql  = kk0 - h * KQ;
#pragma unroll
        for (int i = 0; i < 5; i++) {
            const int c = tid + i * 256;
            if (c < 256) {
                const int row = c >> 2, ch = c & 3;
                const __half* src = g_Ph
                    + ((size_t)h * NTIL + tile) * TT * KQ
                    + (size_t)row * KQ + ql + ch * 8;
                CP16(stb + row * 80 + ch * 16, src);
            } else {
                const int rem = c - 256;                 // 0..1023
                const int row = rem >> 2, ch = rem & 3;  // row 0..255 (c-dim)
                int tg = t0 + ql + ch * 8;
                int sz = (tg < TDIM) ? 16 : 0;
                if (tg >= TDIM) tg = 0;
                const __half* src = g_Vth
                    + ((size_t)h * CDIM + c0 + row) * TDIM + tg;
                CP16Z(stb + 5120 + row * 80 + ch * 16, src, sz);
            }
        }
    };

    load_stage(0, sb);
    CP_COMMIT();
    load_stage(1, sb + AVSTAGE);
    CP_COMMIT();

#pragma unroll 1
    for (int s = 0; s < 96; s++) {
        if (s < 95) { CP_WAIT1(); } else { CP_WAIT0(); }
        __syncthreads();
        if (s + 2 < 96) {
            load_stage(s + 2, sb + ((s + 2) % 3) * AVSTAGE);
            CP_COMMIT();
        }
        const char* st = smem + (s % 3) * AVSTAGE;
        const char* Ah = st;
        const char* Bh = st + 5120;

#pragma unroll
        for (int kk = 0; kk < 32; kk += 16) {
            uint32_t ah[2][4];
#pragma unroll
            for (int i = 0; i < 2; i++) {
                const int b0 = (wm * 32 + i * 16 + g) * 80 + kk * 2 + t4 * 4;
                ah[i][0] = *(const uint32_t*)(Ah + b0);
                ah[i][1] = *(const uint32_t*)(Ah + b0 + 640);
                ah[i][2] = *(const uint32_t*)(Ah + b0 + 16);
                ah[i][3] = *(const uint32_t*)(Ah + b0 + 656);
            }
#pragma unroll
            for (int jj = 0; jj < 2; jj++) {
                uint32_t bh[4][2];
#pragma unroll
                for (int j = 0; j < 4; j++) {
                    const int bb = (wn * 64 + jj * 32 + j * 8 + g) * 80 + kk * 2 + t4 * 4;
                    bh[j][0] = *(const uint32_t*)(Bh + bb);
                    bh[j][1] = *(const uint32_t*)(Bh + bb + 16);
                }
#pragma unroll
                for (int i = 0; i < 2; i++)
#pragma unroll
                    for (int j = 0; j < 4; j++)
                        mma_f16(acc[i][jj * 4 + j], ah[i], bh[j]);
            }
        }
    }

    // epilogue: fp32 out
#pragma unroll
    for (int i = 0; i < 2; i++) {
#pragma unroll
        for (int rr = 0; rr < 2; rr++) {
            const int t = t0 + wm * 32 + i * 16 + g + rr * 8;
#pragma unroll
            for (int j = 0; j < 8; j++) {
                const int c = c0 + wn * 64 + j * 8 + 2 * t4;
                *(float2*)(out + (size_t)t * CDIM + c) =
                    make_float2(acc[i][j][2 * rr], acc[i][j][2 * rr + 1]);
            }
        }
    }
}

// ---------------------------------------------------------------------------
// GroupNorm in place on out
// ---------------------------------------------------------------------------
__global__ __launch_bounds__(256) void gn_kernel(
    float* __restrict__ out,
    const float* __restrict__ wgt,
    const float* __restrict__ bias)
{
    const int t = blockIdx.x;
    const int tid = threadIdx.x;

    float4 v = *(float4*)(out + (size_t)t * CDIM + tid * 4);
    float s  = v.x + v.y + v.z + v.w;
    float sq = v.x * v.x + v.y * v.y + v.z * v.z + v.w * v.w;

#pragma unroll
    for (int off = 8; off > 0; off >>= 1) {
        s  += __shfl_down_sync(0xffffffffu, s,  off, 16);
        sq += __shfl_down_sync(0xffffffffu, sq, off, 16);
    }
    s  = __shfl_sync(0xffffffffu, s,  0, 16);
    sq = __shfl_sync(0xffffffffu, sq, 0, 16);

    float mean = s * (1.f / 64.f);
    float var  = sq * (1.f / 64.f) - mean * mean;
    float rs   = rsqrtf(var + 1e-5f);

    float4 w4 = *(const float4*)(wgt + tid * 4);
    float4 b4 = *(const float4*)(bias + tid * 4);
    v.x = (v.x - mean) * rs * w4.x + b4.x;
    v.y = (v.y - mean) * rs * w4.y + b4.y;
    v.z = (v.z - mean) * rs * w4.z + b4.z;
    v.w = (v.w - mean) * rs * w4.w + b4.w;
    *(float4*)(out + (size_t)t * CDIM + tid * 4) = v;
}

// ---------------------------------------------------------------------------
extern "C" void kernel_launch(void* const* d_in, const int* in_sizes, int n_in,
                              void* d_out, int out_size)
{
    const float* X  = (const float*)d_in[0];
    const float* Wq = (const float*)d_in[1];
    const float* Wk = (const float*)d_in[2];
    const float* Wv = (const float*)d_in[3];
    const float* gw = (const float*)d_in[4];
    const float* gb = (const float*)d_in[5];
    float* out = (float*)d_out;

    prep_x<<<(TDIM * CDIM / 4) / 256, 256>>>(X);
    prep_w<<<dim3(NW / 32, CDIM / 32, 3), dim3(32, 8)>>>(Wq, Wk, Wv);

    cudaFuncSetAttribute(proj_mma, cudaFuncAttributeMaxDynamicSharedMemorySize,
                         SMEM_PROJ);
    proj_mma<<<dim3(16, 32, 3), 256, SMEM_PROJ>>>();

    transpose_v<<<dim3(CDIM / 32, TDIM / 32, HN), dim3(32, 8)>>>();

    cudaFuncSetAttribute(qk_mma, cudaFuncAttributeMaxDynamicSharedMemorySize,
                         SMEM_QK);
    qk_mma<<<dim3(3, NTIL, HN), 256, SMEM_QK>>>();

    cudaFuncSetAttribute(av_mma, cudaFuncAttributeMaxDynamicSharedMemorySize,
                         SMEM_AV);
    av_mma<<<dim3(4, NTIL), 256, SMEM_AV>>>(out);

    gn_kernel<<<TDIM, 256>>>(out, gw, gb);
}

// round 10
// speedup vs baseline: 4.8090x; 1.4756x over previous
#include <cuda_runtime.h>
#include <cuda_fp16.h>
#include <math.h>
#include <stdint.h>

#define TDIM 2048
#define CDIM 1024
#define HN   8
#define NW   8192
#define WIN  320
#define KQ   384
#define TT   64
#define NTIL 32
#define GAMMA 0.96875f

// fp16 operands, all single precision.
__device__ __half g_Xh[(size_t)TDIM * CDIM];
__device__ __half g_Wth[(size_t)3 * NW * CDIM];            // [z][n][k]
__device__ __half g_Qh[(size_t)HN * TDIM * CDIM];
__device__ __half g_Kh[(size_t)HN * TDIM * CDIM];
__device__ __half g_Vh[(size_t)HN * TDIM * CDIM];          // [h][t][c]
__device__ __half g_Vth[(size_t)HN * CDIM * TDIM];         // [h][c][t]
__device__ __half g_Ph[(size_t)HN * NTIL * TT * KQ];       // [h][tile][t][q]

// ---------------------------------------------------------------------------
#define CP16(dst, src) \
    asm volatile("cp.async.cg.shared.global [%0], [%1], 16;" :: "r"(dst), "l"(src))
#define CP16Z(dst, src, sz) \
    asm volatile("cp.async.cg.shared.global [%0], [%1], 16, %2;" :: "r"(dst), "l"(src), "r"(sz))
#define CP_COMMIT() asm volatile("cp.async.commit_group;" ::: "memory")
#define CP_WAIT1()  asm volatile("cp.async.wait_group 1;" ::: "memory")
#define CP_WAIT0()  asm volatile("cp.async.wait_group 0;" ::: "memory")

__device__ __forceinline__ uint32_t smem_u32(const void* p) {
    uint32_t a;
    asm("{ .reg .u64 t; cvta.to.shared.u64 t, %1; cvt.u32.u64 %0, t; }"
        : "=r"(a) : "l"(p));
    return a;
}

__device__ __forceinline__ void mma_f16(float c[4], const uint32_t a[4],
                                        const uint32_t b[2]) {
    asm volatile(
        "mma.sync.aligned.m16n8k16.row.col.f32.f16.f16.f32 "
        "{%0,%1,%2,%3}, {%4,%5,%6,%7}, {%8,%9}, {%0,%1,%2,%3};"
        : "+f"(c[0]), "+f"(c[1]), "+f"(c[2]), "+f"(c[3])
        : "r"(a[0]), "r"(a[1]), "r"(a[2]), "r"(a[3]), "r"(b[0]), "r"(b[1]));
}

__device__ __forceinline__ uint32_t pack_h2(float v0, float v1) {
    __half2 h = __floats2half2_rn(v0, v1);
    return *(uint32_t*)&h;
}

// ---------------------------------------------------------------------------
// Prep: X -> fp16
// ---------------------------------------------------------------------------
__global__ __launch_bounds__(256) void prep_x(const float* __restrict__ X)
{
    int i = blockIdx.x * 256 + threadIdx.x;
    float4 v = ((const float4*)X)[i];
    ((uint2*)g_Xh)[i] = make_uint2(pack_h2(v.x, v.y), pack_h2(v.z, v.w));
}

// ---------------------------------------------------------------------------
// Prep: transpose W [K,N] -> Wt [N,K], fp16
// ---------------------------------------------------------------------------
__global__ __launch_bounds__(256) void prep_w(
    const float* __restrict__ Wq, const float* __restrict__ Wk,
    const float* __restrict__ Wv)
{
    const int z = blockIdx.z;
    const float* W = (z == 0) ? Wq : ((z == 1) ? Wk : Wv);
    const int n0 = blockIdx.x * 32;
    const int k0 = blockIdx.y * 32;

    __shared__ float t[32][33];
    const int tx = threadIdx.x, ty = threadIdx.y;
#pragma unroll
    for (int j = 0; j < 4; j++)
        t[ty + 8 * j][tx] = W[(size_t)(k0 + ty + 8 * j) * NW + n0 + tx];
    __syncthreads();
#pragma unroll
    for (int j = 0; j < 4; j++) {
        float v = t[tx][ty + 8 * j];
        size_t o = ((size_t)z * NW + n0 + ty + 8 * j) * CDIM + k0 + tx;
        g_Wth[o] = __float2half_rn(v);
    }
}

// ---------------------------------------------------------------------------
// Projection: single-term fp16, fused RoPE+SiLU, outputs Q/K/V fp16.
// CTA tile M=128 N=128 Kstage=32, 3-stage pipeline, occ-2 (launch_bounds 2).
// stage: A[128][80B]@0 (10240) | B[128][80B]@10240 (10240); stage 20480.
// ---------------------------------------------------------------------------
#define PSTAGE 20480
#define SMEM_PROJ (3 * PSTAGE)

__device__ __forceinline__ void proj_load_stage(
    uint32_t stb, int tid, int m0, int zn0, int k0)
{
#pragma unroll
    for (int i = 0; i < 4; i++) {
        const int c = tid + i * 256;
        if (c < 512) {
            const int row = c >> 2;
            const int ch  = c & 3;
            const __half* src = g_Xh + (size_t)(m0 + row) * CDIM + k0 + ch * 8;
            CP16(stb + row * 80 + ch * 16, src);
        } else {
            const int rem = c - 512;
            const int row = rem >> 2;
            const int ch  = rem & 3;
            const __half* src = g_Wth + (size_t)(zn0 + row) * CDIM + k0 + ch * 8;
            CP16(stb + 10240 + row * 80 + ch * 16, src);
        }
    }
}

__global__ __launch_bounds__(256, 2) void proj_mma()
{
    extern __shared__ char smem[];
    const uint32_t sb = smem_u32(smem);
    const int tid = threadIdx.x;
    const int wid = tid >> 5;
    const int lane = tid & 31;
    const int wm = wid & 1, wn = wid >> 1;
    const int g = lane >> 2, t4 = lane & 3;

    const int m0 = blockIdx.x * 128;
    const int n0 = blockIdx.y * 128;
    const int z  = blockIdx.z;
    const int zn0 = z * NW + n0;

    float acc[4][4][4];
#pragma unroll
    for (int i = 0; i < 4; i++)
#pragma unroll
        for (int j = 0; j < 4; j++)
#pragma unroll
            for (int q = 0; q < 4; q++) acc[i][j][q] = 0.f;

    proj_load_stage(sb, tid, m0, zn0, 0);
    CP_COMMIT();
    proj_load_stage(sb + PSTAGE, tid, m0, zn0, 32);
    CP_COMMIT();

#pragma unroll 1
    for (int s = 0; s < 32; s++) {
        if (s < 31) { CP_WAIT1(); } else { CP_WAIT0(); }
        __syncthreads();
        if (s + 2 < 32) {
            proj_load_stage(sb + ((s + 2) % 3) * PSTAGE, tid, m0, zn0, (s + 2) * 32);
            CP_COMMIT();
        }
        const char* st = smem + (s % 3) * PSTAGE;
        const char* Ah = st;
        const char* Bh = st + 10240;

#pragma unroll
        for (int kk = 0; kk < 32; kk += 16) {
            uint32_t ah[4][4];
#pragma unroll
            for (int i = 0; i < 4; i++) {
                const int b0 = (wm * 64 + i * 16 + g) * 80 + kk * 2 + t4 * 4;
                ah[i][0] = *(const uint32_t*)(Ah + b0);
                ah[i][1] = *(const uint32_t*)(Ah + b0 + 640);
                ah[i][2] = *(const uint32_t*)(Ah + b0 + 16);
                ah[i][3] = *(const uint32_t*)(Ah + b0 + 656);
            }
            uint32_t bh[4][2];
#pragma unroll
            for (int j = 0; j < 4; j++) {
                const int bb = (wn * 32 + j * 8 + g) * 80 + kk * 2 + t4 * 4;
                bh[j][0] = *(const uint32_t*)(Bh + bb);
                bh[j][1] = *(const uint32_t*)(Bh + bb + 16);
            }
#pragma unroll
            for (int i = 0; i < 4; i++)
#pragma unroll
                for (int j = 0; j < 4; j++)
                    mma_f16(acc[i][j], ah[i], bh[j]);
        }
    }

    // epilogue: RoPE (Q,K cols<64) + SiLU, fp16 store
    const int h  = n0 >> 10;
    const int cbase = (n0 & 1023) + wn * 32 + 2 * t4;
    const bool rope_blk = (z < 2) && ((n0 & 1023) == 0) && (wn < 2);

    __half* Hi = (z == 0) ? g_Qh : ((z == 1) ? g_Kh : g_Vh);
    Hi += (size_t)h * TDIM * CDIM;

#pragma unroll
    for (int i = 0; i < 4; i++) {
#pragma unroll
        for (int rr = 0; rr < 2; rr++) {
            const int r = m0 + wm * 64 + i * 16 + g + rr * 8;
#pragma unroll
            for (int j = 0; j < 4; j++) {
                const int col = cbase + j * 8;
                float v0 = acc[i][j][2 * rr];
                float v1 = acc[i][j][2 * rr + 1];
                if (rope_blk) {
                    int c2 = col >> 1;
                    float invf = (float)exp(-((double)(2 * c2) / 64.0) * log(10000.0));
                    float ang = (float)r * invf;
                    float sn, cs;
                    sincosf(ang, &sn, &cs);
                    float y0 = v0 * cs - v1 * sn;
                    float y1 = v1 * cs + v0 * sn;
                    v0 = y0; v1 = y1;
                }
                v0 = v0 / (1.f + expf(-v0));
                v1 = v1 / (1.f + expf(-v1));
                ((uint32_t*)Hi)[((size_t)r * CDIM + col) >> 1] = pack_h2(v0, v1);
            }
        }
    }
}

// ---------------------------------------------------------------------------
// V transpose: [h][t][c] -> [h][c][t]
// ---------------------------------------------------------------------------
__global__ void transpose_v()
{
    __shared__ unsigned short sh[32][33];
    const int c0 = blockIdx.x * 32;
    const int t0 = blockIdx.y * 32;
    const int h  = blockIdx.z;
    const int tx = threadIdx.x, ty = threadIdx.y;

    const unsigned short* Vh = (const unsigned short*)g_Vh + (size_t)h * TDIM * CDIM;
#pragma unroll
    for (int k = 0; k < 4; k++) {
        int r = ty + 8 * k;
        sh[r][tx] = Vh[(size_t)(t0 + r) * CDIM + c0 + tx];
    }
    __syncthreads();
    unsigned short* Th = (unsigned short*)g_Vth + (size_t)h * CDIM * TDIM;
#pragma unroll
    for (int k = 0; k < 4; k++) {
        int r = ty + 8 * k;
        Th[(size_t)(c0 + r) * TDIM + t0 + tx] = sh[tx][r];
    }
}

// ---------------------------------------------------------------------------
// qk_mma: P = decay * (K Q^T), single-term fp16.
// M=64(t) N=128(q) per block, grid.x=3 covers q in [t0, t0+384), K=1024.
// stage: A[64][80B]@0 (5120) | B[128][80B]@5120 (10240); stage 15360.
// ---------------------------------------------------------------------------
#define QKSTAGE 15360
#define SMEM_QK (3 * QKSTAGE)

__global__ __launch_bounds__(256, 2) void qk_mma()
{
    extern __shared__ char smem[];
    const uint32_t sb = smem_u32(smem);
    const int tid = threadIdx.x;
    const int wid = tid >> 5;
    const int lane = tid & 31;
    const int wm = wid & 1, wn = wid >> 1;
    const int g = lane >> 2, t4 = lane & 3;

    const int qc   = blockIdx.x;          // 0..2
    const int tile = blockIdx.y;
    const int h    = blockIdx.z;
    const int t0   = tile * TT;
    const int q0   = t0 + qc * 128;

    const __half* Kh = g_Kh + (size_t)h * TDIM * CDIM;
    const __half* Qh = g_Qh + (size_t)h * TDIM * CDIM;

    float acc[2][4][4];
#pragma unroll
    for (int i = 0; i < 2; i++)
#pragma unroll
        for (int j = 0; j < 4; j++)
#pragma unroll
            for (int q = 0; q < 4; q++) acc[i][j][q] = 0.f;

    auto load_stage = [&](int s, uint32_t stb) {
        const int k0 = s * 32;
#pragma unroll
        for (int i = 0; i < 3; i++) {
            const int c = tid + i * 256;
            if (c < 256) {
                const int row = c >> 2, ch = c & 3;
                const __half* src = Kh + (size_t)(t0 + row) * CDIM + k0 + ch * 8;
                CP16(stb + row * 80 + ch * 16, src);
            } else {
                const int rem = c - 256;                 // 0..511
                const int row = rem >> 2, ch = rem & 3;
                int q = q0 + row;
                int sz = (q < TDIM) ? 16 : 0;
                if (q >= TDIM) q = 0;
                const __half* src = Qh + (size_t)q * CDIM + k0 + ch * 8;
                CP16Z(stb + 5120 + row * 80 + ch * 16, src, sz);
            }
        }
    };

    load_stage(0, sb);
    CP_COMMIT();
    load_stage(1, sb + QKSTAGE);
    CP_COMMIT();

#pragma unroll 1
    for (int s = 0; s < 32; s++) {
        if (s < 31) { CP_WAIT1(); } else { CP_WAIT0(); }
        __syncthreads();
        if (s + 2 < 32) {
            load_stage(s + 2, sb + ((s + 2) % 3) * QKSTAGE);
            CP_COMMIT();
        }
        const char* st = smem + (s % 3) * QKSTAGE;
        const char* Ah = st;
        const char* Bh = st + 5120;

#pragma unroll
        for (int kk = 0; kk < 32; kk += 16) {
            uint32_t ah[2][4];
#pragma unroll
            for (int i = 0; i < 2; i++) {
                const int b0 = (wm * 32 + i * 16 + g) * 80 + kk * 2 + t4 * 4;
                ah[i][0] = *(const uint32_t*)(Ah + b0);
                ah[i][1] = *(const uint32_t*)(Ah + b0 + 640);
                ah[i][2] = *(const uint32_t*)(Ah + b0 + 16);
                ah[i][3] = *(const uint32_t*)(Ah + b0 + 656);
            }
            uint32_t bh[4][2];
#pragma unroll
            for (int j = 0; j < 4; j++) {
                const int bb = (wn * 32 + j * 8 + g) * 80 + kk * 2 + t4 * 4;
                bh[j][0] = *(const uint32_t*)(Bh + bb);
                bh[j][1] = *(const uint32_t*)(Bh + bb + 16);
            }
#pragma unroll
            for (int i = 0; i < 2; i++)
#pragma unroll
                for (int j = 0; j < 4; j++)
                    mma_f16(acc[i][j], ah[i], bh[j]);
        }
    }

    // epilogue: decay + mask, fp16 store P
    const float lg = log2f(GAMMA);
    __half* Phb = g_Ph + ((size_t)h * NTIL + tile) * TT * KQ;
#pragma unroll
    for (int i = 0; i < 2; i++) {
#pragma unroll
        for (int rr = 0; rr < 2; rr++) {
            const int tl = wm * 32 + i * 16 + g + rr * 8;
            const int t  = t0 + tl;
#pragma unroll
            for (int j = 0; j < 4; j++) {
                const int ql = qc * 128 + wn * 32 + j * 8 + 2 * t4;
                const int q  = t0 + ql;
                float v0 = acc[i][j][2 * rr];
                float v1 = acc[i][j][2 * rr + 1];
                int wd0 = q - t, wd1 = wd0 + 1;
                v0 = (wd0 >= 0 && wd0 < WIN && q < TDIM)
                     ? v0 * exp2f((float)wd0 * lg) : 0.f;
                v1 = (wd1 >= 0 && wd1 < WIN && (q + 1) < TDIM)
                     ? v1 * exp2f((float)wd1 * lg) : 0.f;
                ((uint32_t*)Phb)[((size_t)tl * KQ + ql) >> 1] = pack_h2(v0, v1);
            }
        }
    }
}

// ---------------------------------------------------------------------------
// av_mma: out[t][c] = sum_{h,q} P * V.  Single-term fp16.
// M=64(t) N=128(c) K=8*384=3072. stage: A@0(5120) B@5120(10240); 15360.
// ---------------------------------------------------------------------------
#define AVSTAGE 15360
#define SMEM_AV (3 * AVSTAGE)

__global__ __launch_bounds__(256, 2) void av_mma(float* __restrict__ out)
{
    extern __shared__ char smem[];
    const uint32_t sb = smem_u32(smem);
    const int tid = threadIdx.x;
    const int wid = tid >> 5;
    const int lane = tid & 31;
    const int wm = wid & 1, wn = wid >> 1;
    const int g = lane >> 2, t4 = lane & 3;

    const int cc   = blockIdx.x;      // 0..7
    const int tile = blockIdx.y;
    const int t0   = tile * TT;
    const int c0   = cc * 128;

    float acc[2][4][4];
#pragma unroll
    for (int i = 0; i < 2; i++)
#pragma unroll
        for (int j = 0; j < 4; j++)
#pragma unroll
            for (int q = 0; q < 4; q++) acc[i][j][q] = 0.f;

    auto load_stage = [&](int s, uint32_t stb) {
        const int kk0 = s * 32;
        const int h   = kk0 / KQ;
        const int ql  = kk0 - h * KQ;
#pragma unroll
        for (int i = 0; i < 3; i++) {
            const int c = tid + i * 256;
            if (c < 256) {
                const int row = c >> 2, ch = c & 3;
                const __half* src = g_Ph
                    + ((size_t)h * NTIL + tile) * TT * KQ
                    + (size_t)row * KQ + ql + ch * 8;
                CP16(stb + row * 80 + ch * 16, src);
            } else {
                const int rem = c - 256;                 // 0..511
                const int row = rem >> 2, ch = rem & 3;  // row 0..127 (c-dim)
                int tg = t0 + ql + ch * 8;
                int sz = (tg < TDIM) ? 16 : 0;
                if (tg >= TDIM) tg = 0;
                const __half* src = g_Vth
                    + ((size_t)h * CDIM + c0 + row) * TDIM + tg;
                CP16Z(stb + 5120 + row * 80 + ch * 16, src, sz);
            }
        }
    };

    load_stage(0, sb);
    CP_COMMIT();
    load_stage(1, sb + AVSTAGE);
    CP_COMMIT();

#pragma unroll 1
    for (int s = 0; s < 96; s++) {
        if (s < 95) { CP_WAIT1(); } else { CP_WAIT0(); }
        __syncthreads();
        if (s + 2 < 96) {
            load_stage(s + 2, sb + ((s + 2) % 3) * AVSTAGE);
            CP_COMMIT();
        }
        const char* st = smem + (s % 3) * AVSTAGE;
        const char* Ah = st;
        const char* Bh = st + 5120;

#pragma unroll
        for (int kk = 0; kk < 32; kk += 16) {
            uint32_t ah[2][4];
#pragma unroll
            for (int i = 0; i < 2; i++) {
                const int b0 = (wm * 32 + i * 16 + g) * 80 + kk * 2 + t4 * 4;
                ah[i][0] = *(const uint32_t*)(Ah + b0);
                ah[i][1] = *(const uint32_t*)(Ah + b0 + 640);
                ah[i][2] = *(const uint32_t*)(Ah + b0 + 16);
                ah[i][3] = *(const uint32_t*)(Ah + b0 + 656);
            }
            uint32_t bh[4][2];
#pragma unroll
            for (int j = 0; j < 4; j++) {
                const int bb = (wn * 32 + j * 8 + g) * 80 + kk * 2 + t4 * 4;
                bh[j][0] = *(const uint32_t*)(Bh + bb);
                bh[j][1] = *(const uint32_t*)(Bh + bb + 16);
            }
#pragma unroll
            for (int i = 0; i < 2; i++)
#pragma unroll
                for (int j = 0; j < 4; j++)
                    mma_f16(acc[i][j], ah[i], bh[j]);
        }
    }

    // epilogue: fp32 out
#pragma unroll
    for (int i = 0; i < 2; i++) {
#pragma unroll
        for (int rr = 0; rr < 2; rr++) {
            const int t = t0 + wm * 32 + i * 16 + g + rr * 8;
#pragma unroll
            for (int j = 0; j < 4; j++) {
                const int c = c0 + wn * 32 + j * 8 + 2 * t4;
                *(float2*)(out + (size_t)t * CDIM + c) =
                    make_float2(acc[i][j][2 * rr], acc[i][j][2 * rr + 1]);
            }
        }
    }
}

// ---------------------------------------------------------------------------
// GroupNorm in place on out
// ---------------------------------------------------------------------------
__global__ __launch_bounds__(256) void gn_kernel(
    float* __restrict__ out,
    const float* __restrict__ wgt,
    const float* __restrict__ bias)
{
    const int t = blockIdx.x;
    const int tid = threadIdx.x;

    float4 v = *(float4*)(out + (size_t)t * CDIM + tid * 4);
    float s  = v.x + v.y + v.z + v.w;
    float sq = v.x * v.x + v.y * v.y + v.z * v.z + v.w * v.w;

#pragma unroll
    for (int off = 8; off > 0; off >>= 1) {
        s  += __shfl_down_sync(0xffffffffu, s,  off, 16);
        sq += __shfl_down_sync(0xffffffffu, sq, off, 16);
    }
    s  = __shfl_sync(0xffffffffu, s,  0, 16);
    sq = __shfl_sync(0xffffffffu, sq, 0, 16);

    float mean = s * (1.f / 64.f);
    float var  = sq * (1.f / 64.f) - mean * mean;
    float rs   = rsqrtf(var + 1e-5f);

    float4 w4 = *(const float4*)(wgt + tid * 4);
    float4 b4 = *(const float4*)(bias + tid * 4);
    v.x = (v.x - mean) * rs * w4.x + b4.x;
    v.y = (v.y - mean) * rs * w4.y + b4.y;
    v.z = (v.z - mean) * rs * w4.z + b4.z;
    v.w = (v.w - mean) * rs * w4.w + b4.w;
    *(float4*)(out + (size_t)t * CDIM + tid * 4) = v;
}

// ---------------------------------------------------------------------------
extern "C" void kernel_launch(void* const* d_in, const int* in_sizes, int n_in,
                              void* d_out, int out_size)
{
    const float* X  = (const float*)d_in[0];
    const float* Wq = (const float*)d_in[1];
    const float* Wk = (const float*)d_in[2];
    const float* Wv = (const float*)d_in[3];
    const float* gw = (const float*)d_in[4];
    const float* gb = (const float*)d_in[5];
    float* out = (float*)d_out;

    prep_x<<<(TDIM * CDIM / 4) / 256, 256>>>(X);
    prep_w<<<dim3(NW / 32, CDIM / 32, 3), dim3(32, 8)>>>(Wq, Wk, Wv);

    cudaFuncSetAttribute(proj_mma, cudaFuncAttributeMaxDynamicSharedMemorySize,
                         SMEM_PROJ);
    proj_mma<<<dim3(16, 64, 3), 256, SMEM_PROJ>>>();

    transpose_v<<<dim3(CDIM / 32, TDIM / 32, HN), dim3(32, 8)>>>();

    cudaFuncSetAttribute(qk_mma, cudaFuncAttributeMaxDynamicSharedMemorySize,
                         SMEM_QK);
    qk_mma<<<dim3(3, NTIL, HN), 256, SMEM_QK>>>();

    cudaFuncSetAttribute(av_mma, cudaFuncAttributeMaxDynamicSharedMemorySize,
                         SMEM_AV);
    av_mma<<<dim3(8, NTIL), 256, SMEM_AV>>>(out);

    gn_kernel<<<TDIM, 256>>>(out, gw, gb);
}